// round 5
// baseline (speedup 1.0000x reference)
#include <cuda_runtime.h>

// Problem constants
#define DM     1024            // d_model
#define NB     4               // batch
#define LL     1024            // seq len
#define HH     16              // heads
#define DH     64              // depth per head
#define MROWS  (NB * LL)       // 4096 rows for all projections

// -------- scratch (allocation-free: __device__ globals) --------
__device__ float g_Q[MROWS * DM];
__device__ float g_K[MROWS * DM];
__device__ float g_V[MROWS * DM];
__device__ float g_AO[MROWS * DM];

// ---------------- f32x2 packed-FMA helpers (Blackwell FFMA2) ----------------
__device__ __forceinline__ void ffma2(unsigned long long& d,
                                      unsigned long long a,
                                      unsigned long long b) {
    asm("fma.rn.f32x2 %0, %1, %2, %0;" : "+l"(d) : "l"(a), "l"(b));
}
__device__ __forceinline__ unsigned long long f32x2_dup(float x) {
    unsigned long long r;
    unsigned u = __float_as_uint(x);
    asm("mov.b64 %0, {%1, %1};" : "=l"(r) : "r"(u));
    return r;
}
__device__ __forceinline__ unsigned long long f32x2_pack(float x, float y) {
    unsigned long long r;
    unsigned ux = __float_as_uint(x), uy = __float_as_uint(y);
    asm("mov.b64 %0, {%1, %2};" : "=l"(r) : "r"(ux), "r"(uy));
    return r;
}

// ---------------------------------------------------------------------------
// GEMM: C[M,N] = A[M,K] @ B[K,N] + bias[N]   (all row-major, fp32)
// 128x128 block tile, BK=16, 256 threads, 8x8 per-thread microtile
// accumulated as f32x2 pairs (FFMA2 → full-rate fp32).
// ---------------------------------------------------------------------------
__global__ __launch_bounds__(256, 2)
void sgemm_bias_kernel(const float* __restrict__ A, const float* __restrict__ B,
                       const float* __restrict__ bias, float* __restrict__ C,
                       int M, int N, int K)
{
    __shared__ float As[16][128];   // transposed: As[k][m]
    __shared__ float Bs[16][128];   // Bs[k][n]

    const int tid = threadIdx.x;
    const int tx  = tid & 15;       // col group
    const int ty  = tid >> 4;       // row group
    const int row0 = blockIdx.y * 128;
    const int col0 = blockIdx.x * 128;

    unsigned long long acc[8][4];
    #pragma unroll
    for (int i = 0; i < 8; ++i)
        #pragma unroll
        for (int j = 0; j < 4; ++j) acc[i][j] = 0ull;

    for (int k0 = 0; k0 < K; k0 += 16) {
        // load A tile (128 x 16) transposed into As
        #pragma unroll
        for (int t = 0; t < 2; ++t) {
            int idx = tid + t * 256;
            int r = idx >> 2;             // 0..127
            int c4 = (idx & 3) << 2;      // 0,4,8,12
            float4 v = *(const float4*)(A + (size_t)(row0 + r) * K + k0 + c4);
            As[c4 + 0][r] = v.x;
            As[c4 + 1][r] = v.y;
            As[c4 + 2][r] = v.z;
            As[c4 + 3][r] = v.w;
        }
        // load B tile (16 x 128)
        #pragma unroll
        for (int t = 0; t < 2; ++t) {
            int idx = tid + t * 256;
            int r = idx >> 5;             // 0..15
            int c = (idx & 31) << 2;      // 0..124
            *(float4*)&Bs[r][c] = *(const float4*)(B + (size_t)(k0 + r) * N + col0 + c);
        }
        __syncthreads();

        #pragma unroll
        for (int k = 0; k < 16; ++k) {
            float4 a0 = *(const float4*)&As[k][ty * 8];
            float4 a1 = *(const float4*)&As[k][ty * 8 + 4];
            unsigned long long ad[8];
            ad[0] = f32x2_dup(a0.x); ad[1] = f32x2_dup(a0.y);
            ad[2] = f32x2_dup(a0.z); ad[3] = f32x2_dup(a0.w);
            ad[4] = f32x2_dup(a1.x); ad[5] = f32x2_dup(a1.y);
            ad[6] = f32x2_dup(a1.z); ad[7] = f32x2_dup(a1.w);

            float4 b0f = *(const float4*)&Bs[k][tx * 8];
            float4 b1f = *(const float4*)&Bs[k][tx * 8 + 4];
            unsigned long long bb[4];
            bb[0] = f32x2_pack(b0f.x, b0f.y);
            bb[1] = f32x2_pack(b0f.z, b0f.w);
            bb[2] = f32x2_pack(b1f.x, b1f.y);
            bb[3] = f32x2_pack(b1f.z, b1f.w);

            #pragma unroll
            for (int i = 0; i < 8; ++i) {
                #pragma unroll
                for (int j = 0; j < 4; ++j) ffma2(acc[i][j], ad[i], bb[j]);
            }
        }
        __syncthreads();
    }

    // epilogue: unpack pairs, add bias, store as float2
    #pragma unroll
    for (int i = 0; i < 8; ++i) {
        int row = row0 + ty * 8 + i;
        #pragma unroll
        for (int j = 0; j < 4; ++j) {
            int col = col0 + tx * 8 + j * 2;
            unsigned long long u = acc[i][j];
            float lo = __uint_as_float((unsigned)(u & 0xffffffffull));
            float hi = __uint_as_float((unsigned)(u >> 32));
            float2 out = make_float2(lo + bias[col], hi + bias[col + 1]);
            *(float2*)(C + (size_t)row * N + col) = out;
        }
    }
}

// ---------------------------------------------------------------------------
// Flash-style causal attention with relative-position bias.
//   logits[l][j] = ( q[l]·k[j] + q[l]·pos_emb[2047-(l-j)] ) / 8  (j<=l)
// Tiles: BM=BN=64, 256 threads, 4x4 per-thread. pos_emb diagonal band
// (127 rows x 64) staged in smem per kv-tile. Dynamic smem ~99 KB.
// Q/K/V layout: X[(n*L + l)*DM + h*DH + d]; output same layout → [n,l,h*d].
// ---------------------------------------------------------------------------
#define ATTN_SMEM_FLOATS (3 * 64 * 68 + 64 * 64 + 64 * 128)
#define ATTN_SMEM_BYTES  (ATTN_SMEM_FLOATS * 4)

__global__ __launch_bounds__(256, 2)
void rel_attn_kernel(const float* __restrict__ Q, const float* __restrict__ Kp,
                     const float* __restrict__ Vp, const float* __restrict__ PE,
                     float* __restrict__ O)
{
    extern __shared__ float sm[];
    float* Qs  = sm;                 // [64 d][68]  (transposed, padded)
    float* Ks  = Qs + 64 * 68;       // [64 d][68]
    float* Ps  = Ks + 64 * 68;       // [64 j][68]  (P transposed: Ps[j][i])
    float* Vs  = Ps + 64 * 68;       // [64 j][64]
    float* PEs = Vs + 64 * 64;       // [64 d][128] (band, transposed)

    const int tid = threadIdx.x;
    const int tx  = tid & 15;
    const int ty  = tid >> 4;
    const int qt  = (int)gridDim.x - 1 - (int)blockIdx.x;  // heavy tiles first
    const int l0  = qt * 64;
    const int nh  = blockIdx.y;
    const int n   = nh >> 4;
    const int h   = nh & 15;

    const float* qbase = Q + ((size_t)(n * LL + l0)) * DM + h * DH;

    // load Q tile transposed: Qs[d][i]
    for (int t = tid; t < 64 * 16; t += 256) {
        int r = t >> 4, c4 = (t & 15) << 2;
        float4 v = *(const float4*)(qbase + (size_t)r * DM + c4);
        Qs[(c4 + 0) * 68 + r] = v.x;
        Qs[(c4 + 1) * 68 + r] = v.y;
        Qs[(c4 + 2) * 68 + r] = v.z;
        Qs[(c4 + 3) * 68 + r] = v.w;
    }

    float mrow[4], lrow[4], o[4][4];
    #pragma unroll
    for (int i = 0; i < 4; ++i) {
        mrow[i] = -1e30f; lrow[i] = 0.f;
        #pragma unroll
        for (int j = 0; j < 4; ++j) o[i][j] = 0.f;
    }

    const int base60 = 60 + 4 * (tx - ty);   // band index base, in [0,120]

    for (int jt = 0; jt <= qt; ++jt) {
        const int j0 = jt * 64;
        const float* kbase = Kp + ((size_t)(n * LL + j0)) * DM + h * DH;
        const float* vbase = Vp + ((size_t)(n * LL + j0)) * DM + h * DH;

        // K tile transposed
        for (int t = tid; t < 64 * 16; t += 256) {
            int r = t >> 4, c4 = (t & 15) << 2;
            float4 v = *(const float4*)(kbase + (size_t)r * DM + c4);
            Ks[(c4 + 0) * 68 + r] = v.x;
            Ks[(c4 + 1) * 68 + r] = v.y;
            Ks[(c4 + 2) * 68 + r] = v.z;
            Ks[(c4 + 3) * 68 + r] = v.w;
        }
        // V tile row-major
        for (int t = tid; t < 64 * 16; t += 256) {
            int r = t >> 4, c4 = (t & 15) << 2;
            *(float4*)(Vs + r * 64 + c4) =
                *(const float4*)(vbase + (size_t)r * DM + c4);
        }
        // pos_emb diagonal band: rows pebase..pebase+126, transposed into PEs[d][r]
        const int pebase = 1984 - l0 + j0;   // >= 1024 always
        for (int t = tid; t < 127 * 16; t += 256) {
            int r = t >> 4, c4 = (t & 15) << 2;
            int gr = pebase + r;
            float4 v = make_float4(0.f, 0.f, 0.f, 0.f);
            if (gr < 2048) v = *(const float4*)(PE + (size_t)gr * DH + c4);
            PEs[(c4 + 0) * 128 + r] = v.x;
            PEs[(c4 + 1) * 128 + r] = v.y;
            PEs[(c4 + 2) * 128 + r] = v.z;
            PEs[(c4 + 3) * 128 + r] = v.w;
        }
        __syncthreads();

        // scores: acc[ii][jj] = sum_d q * (k + pe_band)
        float acc[4][4];
        #pragma unroll
        for (int i = 0; i < 4; ++i)
            #pragma unroll
            for (int j = 0; j < 4; ++j) acc[i][j] = 0.f;

        #pragma unroll 2
        for (int d = 0; d < 64; ++d) {
            float4 af = *(const float4*)(Qs + d * 68 + ty * 4);
            float4 bf = *(const float4*)(Ks + d * 68 + tx * 4);
            float pe[7];
            #pragma unroll
            for (int t = 0; t < 7; ++t) pe[t] = PEs[d * 128 + base60 + t];
            float a[4] = {af.x, af.y, af.z, af.w};
            float b[4] = {bf.x, bf.y, bf.z, bf.w};
            #pragma unroll
            for (int ii = 0; ii < 4; ++ii)
                #pragma unroll
                for (int jj = 0; jj < 4; ++jj)
                    acc[ii][jj] += a[ii] * (b[jj] + pe[jj - ii + 3]);
        }

        // online softmax (rows owned by 16-lane groups sharing ty)
        #pragma unroll
        for (int ii = 0; ii < 4; ++ii) {
            const int gi = l0 + ty * 4 + ii;
            float sv[4];
            float rmax = -1e30f;
            #pragma unroll
            for (int jj = 0; jj < 4; ++jj) {
                const int gj = j0 + tx * 4 + jj;
                float s = acc[ii][jj] * 0.125f;        // /sqrt(64)
                if (gj > gi) s -= 1.0e9f;              // causal mask (as reference)
                sv[jj] = s;
                rmax = fmaxf(rmax, s);
            }
            #pragma unroll
            for (int st = 1; st < 16; st <<= 1)
                rmax = fmaxf(rmax, __shfl_xor_sync(0xffffffffu, rmax, st));

            const float mnew  = fmaxf(mrow[ii], rmax);
            const float alpha = __expf(mrow[ii] - mnew);
            mrow[ii] = mnew;

            float rsum = 0.f;
            #pragma unroll
            for (int jj = 0; jj < 4; ++jj) {
                sv[jj] = __expf(sv[jj] - mnew);
                rsum += sv[jj];
            }
            #pragma unroll
            for (int st = 1; st < 16; st <<= 1)
                rsum += __shfl_xor_sync(0xffffffffu, rsum, st);

            lrow[ii] = lrow[ii] * alpha + rsum;
            #pragma unroll
            for (int dd = 0; dd < 4; ++dd) o[ii][dd] *= alpha;
            #pragma unroll
            for (int jj = 0; jj < 4; ++jj)
                Ps[(tx * 4 + jj) * 68 + ty * 4 + ii] = sv[jj];
        }
        __syncthreads();

        // O += P @ V
        #pragma unroll 4
        for (int j = 0; j < 64; ++j) {
            float4 pf = *(const float4*)(Ps + j * 68 + ty * 4);
            float4 vf = *(const float4*)(Vs + j * 64 + tx * 4);
            float p4[4] = {pf.x, pf.y, pf.z, pf.w};
            float v4[4] = {vf.x, vf.y, vf.z, vf.w};
            #pragma unroll
            for (int ii = 0; ii < 4; ++ii)
                #pragma unroll
                for (int dd = 0; dd < 4; ++dd)
                    o[ii][dd] += p4[ii] * v4[dd];
        }
        __syncthreads();
    }

    // epilogue: normalize, store [n, l, h*DH + d]
    float* obase = O + ((size_t)(n * LL + l0)) * DM + h * DH;
    #pragma unroll
    for (int ii = 0; ii < 4; ++ii) {
        const float inv = 1.0f / lrow[ii];
        #pragma unroll
        for (int dd = 0; dd < 4; ++dd)
            obase[(size_t)(ty * 4 + ii) * DM + tx * 4 + dd] = o[ii][dd] * inv;
    }
}

// ---------------------------------------------------------------------------
extern "C" void kernel_launch(void* const* d_in, const int* in_sizes, int n_in,
                              void* d_out, int out_size)
{
    const float* q_in = (const float*)d_in[0];
    const float* k_in = (const float*)d_in[1];
    const float* v_in = (const float*)d_in[2];
    /* d_in[3] = mask: causal triu, implemented analytically */
    const float* Wq = (const float*)d_in[4];
    const float* bq = (const float*)d_in[5];
    const float* Wk = (const float*)d_in[6];
    const float* bk = (const float*)d_in[7];
    const float* Wv = (const float*)d_in[8];
    const float* bv = (const float*)d_in[9];
    const float* Wo = (const float*)d_in[10];
    const float* bo = (const float*)d_in[11];
    const float* pe = (const float*)d_in[12];
    float* out = (float*)d_out;

    float *Qp, *Kp, *Vp, *AOp;
    cudaGetSymbolAddress((void**)&Qp,  g_Q);
    cudaGetSymbolAddress((void**)&Kp,  g_K);
    cudaGetSymbolAddress((void**)&Vp,  g_V);
    cudaGetSymbolAddress((void**)&AOp, g_AO);

    cudaFuncSetAttribute(rel_attn_kernel,
                         cudaFuncAttributeMaxDynamicSharedMemorySize,
                         ATTN_SMEM_BYTES);

    dim3 gemm_grid(DM / 128, MROWS / 128);   // (8, 32)

    sgemm_bias_kernel<<<gemm_grid, 256>>>(q_in, Wq, bq, Qp,  MROWS, DM, DM);
    sgemm_bias_kernel<<<gemm_grid, 256>>>(k_in, Wk, bk, Kp,  MROWS, DM, DM);
    sgemm_bias_kernel<<<gemm_grid, 256>>>(v_in, Wv, bv, Vp,  MROWS, DM, DM);

    rel_attn_kernel<<<dim3(LL / 64, NB * HH), 256, ATTN_SMEM_BYTES>>>(
        Qp, Kp, Vp, pe, AOp);

    sgemm_bias_kernel<<<gemm_grid, 256>>>(AOp, Wo, bo, out, MROWS, DM, DM);
}

// round 8
// speedup vs baseline: 1.3367x; 1.3367x over previous
#include <cuda_runtime.h>
#include <cuda_bf16.h>
#include <cstdint>

// Problem constants
#define DM     1024
#define NB     4
#define LL     1024
#define HH     16
#define DH     64
#define MROWS  (NB * LL)

// -------- scratch (allocation-free: __device__ globals) --------
__device__ float g_Q[MROWS * DM];
__device__ float g_K[MROWS * DM];
__device__ float g_V[MROWS * DM];
__device__ float g_AO[MROWS * DM];
__device__ __nv_bfloat16 g_Ah[MROWS * DM];
__device__ __nv_bfloat16 g_Al[MROWS * DM];
__device__ __nv_bfloat16 g_BhT[DM * DM];
__device__ __nv_bfloat16 g_BlT[DM * DM];

// =========================== helpers =======================================
__device__ __forceinline__ uint32_t smem_to_u32(const void* p) {
    uint32_t a;
    asm("{ .reg .u64 t; cvta.to.shared.u64 t, %1; cvt.u32.u64 %0, t; }"
        : "=r"(a) : "l"(p));
    return a;
}

#define LDMX4(r, addr)                                                        \
    asm volatile("ldmatrix.sync.aligned.m8n8.x4.shared.b16 "                  \
                 "{%0,%1,%2,%3}, [%4];"                                       \
                 : "=r"((r)[0]), "=r"((r)[1]), "=r"((r)[2]), "=r"((r)[3])     \
                 : "r"(addr))

__device__ __forceinline__ void mma_bf16(float* d, const uint32_t* a,
                                         uint32_t b0, uint32_t b1) {
    asm volatile(
        "mma.sync.aligned.m16n8k16.row.col.f32.bf16.bf16.f32 "
        "{%0,%1,%2,%3}, {%4,%5,%6,%7}, {%8,%9}, {%0,%1,%2,%3};"
        : "+f"(d[0]), "+f"(d[1]), "+f"(d[2]), "+f"(d[3])
        : "r"(a[0]), "r"(a[1]), "r"(a[2]), "r"(a[3]), "r"(b0), "r"(b1));
}

// ===========================================================================
// split fp32 -> (hi bf16, lo bf16), elementwise
// ===========================================================================
__global__ void split_bf16_kernel(const float* __restrict__ X,
                                  __nv_bfloat16* __restrict__ H,
                                  __nv_bfloat16* __restrict__ L, int n)
{
    int i = (blockIdx.x * blockDim.x + threadIdx.x) * 4;
    if (i >= n) return;
    float4 v = *(const float4*)(X + i);
    __nv_bfloat16 h0 = __float2bfloat16_rn(v.x);
    __nv_bfloat16 h1 = __float2bfloat16_rn(v.y);
    __nv_bfloat16 h2 = __float2bfloat16_rn(v.z);
    __nv_bfloat16 h3 = __float2bfloat16_rn(v.w);
    __nv_bfloat16 l0 = __float2bfloat16_rn(v.x - __bfloat162float(h0));
    __nv_bfloat16 l1 = __float2bfloat16_rn(v.y - __bfloat162float(h1));
    __nv_bfloat16 l2 = __float2bfloat16_rn(v.z - __bfloat162float(h2));
    __nv_bfloat16 l3 = __float2bfloat16_rn(v.w - __bfloat162float(h3));
    *(__nv_bfloat162*)(H + i)     = __halves2bfloat162(h0, h1);
    *(__nv_bfloat162*)(H + i + 2) = __halves2bfloat162(h2, h3);
    *(__nv_bfloat162*)(L + i)     = __halves2bfloat162(l0, l1);
    *(__nv_bfloat162*)(L + i + 2) = __halves2bfloat162(l2, l3);
}

// ===========================================================================
// transpose + split: W[K][N] fp32 -> HT/LT[N][K] bf16
// ===========================================================================
__global__ void splitT_bf16_kernel(const float* __restrict__ W,
                                   __nv_bfloat16* __restrict__ HT,
                                   __nv_bfloat16* __restrict__ LT)
{
    __shared__ float t[32][33];
    const int bx = blockIdx.x * 32;   // n
    const int by = blockIdx.y * 32;   // k
    const int x = threadIdx.x, y = threadIdx.y;   // 32 x 8
    #pragma unroll
    for (int j = 0; j < 32; j += 8)
        t[y + j][x] = W[(size_t)(by + y + j) * DM + bx + x];
    __syncthreads();
    #pragma unroll
    for (int j = 0; j < 32; j += 8) {
        float v = t[x][y + j];                 // = W[by+x][bx+y+j]
        __nv_bfloat16 h = __float2bfloat16_rn(v);
        __nv_bfloat16 l = __float2bfloat16_rn(v - __bfloat162float(h));
        size_t o = (size_t)(bx + y + j) * DM + by + x;
        HT[o] = h;
        LT[o] = l;
    }
}

// ===========================================================================
// HMMA split-bf16 GEMM: C[M,N] = A @ W + bias via AhBh + AhBl + AlBh.
// A split: Ah/Al [M,K]; W split transposed: BhT/BlT [N,K].
// 128x128 block, 8 warps (2 x 4), warp tile 64x32, K-chunk 32.
// Smem rows padded to 40 bf16 (80B) -> conflict-free ldmatrix.
// ===========================================================================
#define SK 40

__global__ __launch_bounds__(256)
void hmma_gemm_kernel(const __nv_bfloat16* __restrict__ Ah,
                      const __nv_bfloat16* __restrict__ Al,
                      const __nv_bfloat16* __restrict__ BhT,
                      const __nv_bfloat16* __restrict__ BlT,
                      const float* __restrict__ bias,
                      float* __restrict__ C, int M, int N, int K)
{
    __shared__ __nv_bfloat16 sAh[128][SK], sAl[128][SK];
    __shared__ __nv_bfloat16 sBh[128][SK], sBl[128][SK];

    const int tid  = threadIdx.x;
    const int lane = tid & 31;
    const int wid  = tid >> 5;
    const int wm   = wid & 1;          // warp row (2)
    const int wn   = wid >> 1;         // warp col (4)
    const int row0 = blockIdx.y * 128;
    const int col0 = blockIdx.x * 128;

    float acc[4][4][4];
    #pragma unroll
    for (int i = 0; i < 4; ++i)
        #pragma unroll
        for (int j = 0; j < 4; ++j)
            #pragma unroll
            for (int k = 0; k < 4; ++k) acc[i][j][k] = 0.f;

    // ldmatrix per-lane base addresses
    // A x4 tiles: (m0-7,k0-7)(m8-15,k0-7)(m0-7,k8-15)(m8-15,k8-15)
    const int aRow = wm * 64 + ((lane >> 3) & 1) * 8 + (lane & 7);
    const int aK   = ((lane >> 4) & 1) * 8;
    // B x4 tiles: (n0-7,k0-7)(n0-7,k8-15)(n8-15,k0-7)(n8-15,k8-15)
    const int bRow = wn * 32 + ((lane >> 4) & 1) * 8 + (lane & 7);
    const int bK   = ((lane >> 3) & 1) * 8;

    const uint32_t uAh = smem_to_u32(&sAh[aRow][aK]);
    const uint32_t uAl = smem_to_u32(&sAl[aRow][aK]);
    const uint32_t uBh = smem_to_u32(&sBh[bRow][bK]);
    const uint32_t uBl = smem_to_u32(&sBl[bRow][bK]);

    const __nv_bfloat16* gAh = Ah  + (size_t)row0 * K;
    const __nv_bfloat16* gAl = Al  + (size_t)row0 * K;
    const __nv_bfloat16* gBh = BhT + (size_t)col0 * K;
    const __nv_bfloat16* gBl = BlT + (size_t)col0 * K;

    const int lr  = tid >> 2;            // 0..63
    const int lc  = (tid & 3) * 8;       // elem offset (8 elems = 16B)

    for (int kc = 0; kc < K; kc += 32) {
        const size_t o1 = (size_t)lr * K + kc + lc;
        const size_t o2 = (size_t)(lr + 64) * K + kc + lc;
        *(uint4*)&sAh[lr][lc]      = *(const uint4*)(gAh + o1);
        *(uint4*)&sAh[lr + 64][lc] = *(const uint4*)(gAh + o2);
        *(uint4*)&sAl[lr][lc]      = *(const uint4*)(gAl + o1);
        *(uint4*)&sAl[lr + 64][lc] = *(const uint4*)(gAl + o2);
        *(uint4*)&sBh[lr][lc]      = *(const uint4*)(gBh + o1);
        *(uint4*)&sBh[lr + 64][lc] = *(const uint4*)(gBh + o2);
        *(uint4*)&sBl[lr][lc]      = *(const uint4*)(gBl + o1);
        *(uint4*)&sBl[lr + 64][lc] = *(const uint4*)(gBl + o2);
        __syncthreads();

        #pragma unroll
        for (int ks = 0; ks < 32; ks += 16) {
            uint32_t ahf[4][4], alf[4][4], bhf[2][4], blf[2][4];
            #pragma unroll
            for (int mt = 0; mt < 4; ++mt) {
                LDMX4(ahf[mt], uAh + mt * (16 * SK * 2) + ks * 2);
                LDMX4(alf[mt], uAl + mt * (16 * SK * 2) + ks * 2);
            }
            #pragma unroll
            for (int p = 0; p < 2; ++p) {
                LDMX4(bhf[p], uBh + p * (16 * SK * 2) + ks * 2);
                LDMX4(blf[p], uBl + p * (16 * SK * 2) + ks * 2);
            }
            #pragma unroll
            for (int mt = 0; mt < 4; ++mt) {
                #pragma unroll
                for (int nt = 0; nt < 4; ++nt) {
                    const uint32_t* bh2 = &bhf[nt >> 1][(nt & 1) * 2];
                    const uint32_t* bl2 = &blf[nt >> 1][(nt & 1) * 2];
                    mma_bf16(acc[mt][nt], ahf[mt], bh2[0], bh2[1]);
                    mma_bf16(acc[mt][nt], ahf[mt], bl2[0], bl2[1]);
                    mma_bf16(acc[mt][nt], alf[mt], bh2[0], bh2[1]);
                }
            }
        }
        __syncthreads();
    }

    // epilogue: D frag layout m16n8 -> rows lane/4, lane/4+8; cols 2*(lane%4)
    #pragma unroll
    for (int mt = 0; mt < 4; ++mt) {
        const int r1 = row0 + wm * 64 + mt * 16 + (lane >> 2);
        const int r2 = r1 + 8;
        #pragma unroll
        for (int nt = 0; nt < 4; ++nt) {
            const int c = col0 + wn * 32 + nt * 8 + (lane & 3) * 2;
            const float b0 = bias[c], b1 = bias[c + 1];
            *(float2*)(C + (size_t)r1 * N + c) =
                make_float2(acc[mt][nt][0] + b0, acc[mt][nt][1] + b1);
            *(float2*)(C + (size_t)r2 * N + c) =
                make_float2(acc[mt][nt][2] + b0, acc[mt][nt][3] + b1);
        }
    }
}

// ===========================================================================
// Flash-style causal attention with relative-position bias (fp32).
// PE band fetched as two conflict-free LDS.128 per d (base60 % 4 == 0).
// ===========================================================================
#define ATTN_SMEM_FLOATS (3 * 64 * 68 + 64 * 64 + 64 * 128)
#define ATTN_SMEM_BYTES  (ATTN_SMEM_FLOATS * 4)

__global__ __launch_bounds__(256, 2)
void rel_attn_kernel(const float* __restrict__ Q, const float* __restrict__ Kp,
                     const float* __restrict__ Vp, const float* __restrict__ PE,
                     float* __restrict__ O)
{
    extern __shared__ float sm[];
    float* Qs  = sm;
    float* Ks  = Qs + 64 * 68;
    float* Ps  = Ks + 64 * 68;
    float* Vs  = Ps + 64 * 68;
    float* PEs = Vs + 64 * 64;

    const int tid = threadIdx.x;
    const int tx  = tid & 15;
    const int ty  = tid >> 4;
    const int qt  = (int)gridDim.x - 1 - (int)blockIdx.x;
    const int l0  = qt * 64;
    const int nh  = blockIdx.y;
    const int n   = nh >> 4;
    const int h   = nh & 15;

    const float* qbase = Q + ((size_t)(n * LL + l0)) * DM + h * DH;

    for (int t = tid; t < 64 * 16; t += 256) {
        int r = t >> 4, c4 = (t & 15) << 2;
        float4 v = *(const float4*)(qbase + (size_t)r * DM + c4);
        Qs[(c4 + 0) * 68 + r] = v.x;
        Qs[(c4 + 1) * 68 + r] = v.y;
        Qs[(c4 + 2) * 68 + r] = v.z;
        Qs[(c4 + 3) * 68 + r] = v.w;
    }

    float mrow[4], lrow[4], o[4][4];
    #pragma unroll
    for (int i = 0; i < 4; ++i) {
        mrow[i] = -1e30f; lrow[i] = 0.f;
        #pragma unroll
        for (int j = 0; j < 4; ++j) o[i][j] = 0.f;
    }

    const int base60 = 60 + 4 * (tx - ty);   // multiple of 4, in [0,120]

    for (int jt = 0; jt <= qt; ++jt) {
        const int j0 = jt * 64;
        const float* kbase = Kp + ((size_t)(n * LL + j0)) * DM + h * DH;
        const float* vbase = Vp + ((size_t)(n * LL + j0)) * DM + h * DH;

        for (int t = tid; t < 64 * 16; t += 256) {
            int r = t >> 4, c4 = (t & 15) << 2;
            float4 v = *(const float4*)(kbase + (size_t)r * DM + c4);
            Ks[(c4 + 0) * 68 + r] = v.x;
            Ks[(c4 + 1) * 68 + r] = v.y;
            Ks[(c4 + 2) * 68 + r] = v.z;
            Ks[(c4 + 3) * 68 + r] = v.w;
        }
        for (int t = tid; t < 64 * 16; t += 256) {
            int r = t >> 4, c4 = (t & 15) << 2;
            *(float4*)(Vs + r * 64 + c4) =
                *(const float4*)(vbase + (size_t)r * DM + c4);
        }
        const int pebase = 1984 - l0 + j0;
        for (int t = tid; t < 127 * 16; t += 256) {
            int r = t >> 4, c4 = (t & 15) << 2;
            int gr = pebase + r;
            float4 v = make_float4(0.f, 0.f, 0.f, 0.f);
            if (gr < 2048) v = *(const float4*)(PE + (size_t)gr * DH + c4);
            PEs[(c4 + 0) * 128 + r] = v.x;
            PEs[(c4 + 1) * 128 + r] = v.y;
            PEs[(c4 + 2) * 128 + r] = v.z;
            PEs[(c4 + 3) * 128 + r] = v.w;
        }
        __syncthreads();

        float acc[4][4];
        #pragma unroll
        for (int i = 0; i < 4; ++i)
            #pragma unroll
            for (int j = 0; j < 4; ++j) acc[i][j] = 0.f;

        #pragma unroll 2
        for (int d = 0; d < 64; ++d) {
            float4 af = *(const float4*)(Qs + d * 68 + ty * 4);
            float4 bf = *(const float4*)(Ks + d * 68 + tx * 4);
            float4 p0 = *(const float4*)(PEs + d * 128 + base60);
            float4 p1 = *(const float4*)(PEs + d * 128 + base60 + 4);
            float pe[8] = {p0.x, p0.y, p0.z, p0.w, p1.x, p1.y, p1.z, p1.w};
            float a[4] = {af.x, af.y, af.z, af.w};
            float b[4] = {bf.x, bf.y, bf.z, bf.w};
            #pragma unroll
            for (int ii = 0; ii < 4; ++ii)
                #pragma unroll
                for (int jj = 0; jj < 4; ++jj)
                    acc[ii][jj] += a[ii] * (b[jj] + pe[jj - ii + 3]);
        }

        #pragma unroll
        for (int ii = 0; ii < 4; ++ii) {
            const int gi = l0 + ty * 4 + ii;
            float sv[4];
            float rmax = -1e30f;
            #pragma unroll
            for (int jj = 0; jj < 4; ++jj) {
                const int gj = j0 + tx * 4 + jj;
                float s = acc[ii][jj] * 0.125f;
                if (gj > gi) s -= 1.0e9f;
                sv[jj] = s;
                rmax = fmaxf(rmax, s);
            }
            #pragma unroll
            for (int st = 1; st < 16; st <<= 1)
                rmax = fmaxf(rmax, __shfl_xor_sync(0xffffffffu, rmax, st));

            const float mnew  = fmaxf(mrow[ii], rmax);
            const float alpha = __expf(mrow[ii] - mnew);
            mrow[ii] = mnew;

            float rsum = 0.f;
            #pragma unroll
            for (int jj = 0; jj < 4; ++jj) {
                sv[jj] = __expf(sv[jj] - mnew);
                rsum += sv[jj];
            }
            #pragma unroll
            for (int st = 1; st < 16; st <<= 1)
                rsum += __shfl_xor_sync(0xffffffffu, rsum, st);

            lrow[ii] = lrow[ii] * alpha + rsum;
            #pragma unroll
            for (int dd = 0; dd < 4; ++dd) o[ii][dd] *= alpha;
            #pragma unroll
            for (int jj = 0; jj < 4; ++jj)
                Ps[(tx * 4 + jj) * 68 + ty * 4 + ii] = sv[jj];
        }
        __syncthreads();

        #pragma unroll 4
        for (int j = 0; j < 64; ++j) {
            float4 pf = *(const float4*)(Ps + j * 68 + ty * 4);
            float4 vf = *(const float4*)(Vs + j * 64 + tx * 4);
            float p4[4] = {pf.x, pf.y, pf.z, pf.w};
            float v4[4] = {vf.x, vf.y, vf.z, vf.w};
            #pragma unroll
            for (int ii = 0; ii < 4; ++ii)
                #pragma unroll
                for (int dd = 0; dd < 4; ++dd)
                    o[ii][dd] += p4[ii] * v4[dd];
        }
        __syncthreads();
    }

    float* obase = O + ((size_t)(n * LL + l0)) * DM + h * DH;
    #pragma unroll
    for (int ii = 0; ii < 4; ++ii) {
        const float inv = 1.0f / lrow[ii];
        #pragma unroll
        for (int dd = 0; dd < 4; ++dd)
            obase[(size_t)(ty * 4 + ii) * DM + tx * 4 + dd] = o[ii][dd] * inv;
    }
}

// ===========================================================================
extern "C" void kernel_launch(void* const* d_in, const int* in_sizes, int n_in,
                              void* d_out, int out_size)
{
    const float* q_in = (const float*)d_in[0];
    const float* k_in = (const float*)d_in[1];
    const float* v_in = (const float*)d_in[2];
    const float* Wq = (const float*)d_in[4];
    const float* bq = (const float*)d_in[5];
    const float* Wk = (const float*)d_in[6];
    const float* bk = (const float*)d_in[7];
    const float* Wv = (const float*)d_in[8];
    const float* bv = (const float*)d_in[9];
    const float* Wo = (const float*)d_in[10];
    const float* bo = (const float*)d_in[11];
    const float* pe = (const float*)d_in[12];
    float* out = (float*)d_out;

    float *Qp, *Kp, *Vp, *AOp;
    __nv_bfloat16 *Ahp, *Alp, *BhTp, *BlTp;
    cudaGetSymbolAddress((void**)&Qp,   g_Q);
    cudaGetSymbolAddress((void**)&Kp,   g_K);
    cudaGetSymbolAddress((void**)&Vp,   g_V);
    cudaGetSymbolAddress((void**)&AOp,  g_AO);
    cudaGetSymbolAddress((void**)&Ahp,  g_Ah);
    cudaGetSymbolAddress((void**)&Alp,  g_Al);
    cudaGetSymbolAddress((void**)&BhTp, g_BhT);
    cudaGetSymbolAddress((void**)&BlTp, g_BlT);

    cudaFuncSetAttribute(rel_attn_kernel,
                         cudaFuncAttributeMaxDynamicSharedMemorySize,
                         ATTN_SMEM_BYTES);

    const int nA = MROWS * DM;
    const dim3 sp_grid(nA / 4 / 256);
    const dim3 tr_grid(DM / 32, DM / 32), tr_blk(32, 8);
    const dim3 mm_grid(DM / 128, MROWS / 128);   // (8, 32)

    // Q = q_in @ Wq + bq
    split_bf16_kernel<<<sp_grid, 256>>>(q_in, Ahp, Alp, nA);
    splitT_bf16_kernel<<<tr_grid, tr_blk>>>(Wq, BhTp, BlTp);
    hmma_gemm_kernel<<<mm_grid, 256>>>(Ahp, Alp, BhTp, BlTp, bq, Qp,
                                       MROWS, DM, DM);

    // K = k_in @ Wk + bk
    split_bf16_kernel<<<sp_grid, 256>>>(k_in, Ahp, Alp, nA);
    splitT_bf16_kernel<<<tr_grid, tr_blk>>>(Wk, BhTp, BlTp);
    hmma_gemm_kernel<<<mm_grid, 256>>>(Ahp, Alp, BhTp, BlTp, bk, Kp,
                                       MROWS, DM, DM);

    // V = v_in @ Wv + bv
    split_bf16_kernel<<<sp_grid, 256>>>(v_in, Ahp, Alp, nA);
    splitT_bf16_kernel<<<tr_grid, tr_blk>>>(Wv, BhTp, BlTp);
    hmma_gemm_kernel<<<mm_grid, 256>>>(Ahp, Alp, BhTp, BlTp, bv, Vp,
                                       MROWS, DM, DM);

    // attention
    rel_attn_kernel<<<dim3(LL / 64, NB * HH), 256, ATTN_SMEM_BYTES>>>(
        Qp, Kp, Vp, pe, AOp);

    // out = AO @ Wo + bo
    split_bf16_kernel<<<sp_grid, 256>>>(AOp, Ahp, Alp, nA);
    splitT_bf16_kernel<<<tr_grid, tr_blk>>>(Wo, BhTp, BlTp);
    hmma_gemm_kernel<<<mm_grid, 256>>>(Ahp, Alp, BhTp, BlTp, bo, out,
                                       MROWS, DM, DM);
}

// round 12
// speedup vs baseline: 2.0748x; 1.5522x over previous
#include <cuda_runtime.h>
#include <cuda_bf16.h>
#include <cstdint>

// Problem constants
#define DM     1024
#define NB     4
#define LL     1024
#define HH     16
#define DH     64
#define MROWS  (NB * LL)

// -------- scratch (allocation-free: __device__ globals) --------
__device__ float g_Q[MROWS * DM];
__device__ float g_K[MROWS * DM];
__device__ float g_V[MROWS * DM];
__device__ float g_AO[MROWS * DM];
__device__ __nv_bfloat16 g_Ah[MROWS * DM];
__device__ __nv_bfloat16 g_Al[MROWS * DM];
__device__ __nv_bfloat16 g_BhT[DM * DM];
__device__ __nv_bfloat16 g_BlT[DM * DM];

// =========================== helpers =======================================
__device__ __forceinline__ uint32_t smem_to_u32(const void* p) {
    uint32_t a;
    asm("{ .reg .u64 t; cvta.to.shared.u64 t, %1; cvt.u32.u64 %0, t; }"
        : "=r"(a) : "l"(p));
    return a;
}

#define LDMX4(r, addr)                                                        \
    asm volatile("ldmatrix.sync.aligned.m8n8.x4.shared.b16 "                  \
                 "{%0,%1,%2,%3}, [%4];"                                       \
                 : "=r"((r)[0]), "=r"((r)[1]), "=r"((r)[2]), "=r"((r)[3])     \
                 : "r"(addr))

__device__ __forceinline__ void mma_bf16(float* d, const uint32_t* a,
                                         uint32_t b0, uint32_t b1) {
    asm volatile(
        "mma.sync.aligned.m16n8k16.row.col.f32.bf16.bf16.f32 "
        "{%0,%1,%2,%3}, {%4,%5,%6,%7}, {%8,%9}, {%0,%1,%2,%3};"
        : "+f"(d[0]), "+f"(d[1]), "+f"(d[2]), "+f"(d[3])
        : "r"(a[0]), "r"(a[1]), "r"(a[2]), "r"(a[3]), "r"(b0), "r"(b1));
}

// fast exp on fma pipe (x <= 0): e^x = 2^(x*log2e), deg-5 poly for 2^f
__device__ __forceinline__ float fast_exp(float x) {
    float y = fmaxf(x * 1.44269504f, -126.0f);
    float r = rintf(y);
    float f = y - r;
    int   e = (int)r;
    float p = 1.33336e-3f;
    p = fmaf(p, f, 9.61812e-3f);
    p = fmaf(p, f, 5.55041e-2f);
    p = fmaf(p, f, 2.40226e-1f);
    p = fmaf(p, f, 6.93147e-1f);
    p = fmaf(p, f, 1.0f);
    return __int_as_float(__float_as_int(p) + (e << 23));
}

__device__ __forceinline__ uint32_t pack_bf2(float a, float b) {
    __nv_bfloat162 t = __halves2bfloat162(__float2bfloat16_rn(a),
                                          __float2bfloat16_rn(b));
    return *reinterpret_cast<uint32_t*>(&t);
}

// ===========================================================================
// split fp32 -> (hi bf16, lo bf16), elementwise
// ===========================================================================
__global__ void split_bf16_kernel(const float* __restrict__ X,
                                  __nv_bfloat16* __restrict__ H,
                                  __nv_bfloat16* __restrict__ L, int n)
{
    int i = (blockIdx.x * blockDim.x + threadIdx.x) * 4;
    if (i >= n) return;
    float4 v = *(const float4*)(X + i);
    __nv_bfloat16 h0 = __float2bfloat16_rn(v.x);
    __nv_bfloat16 h1 = __float2bfloat16_rn(v.y);
    __nv_bfloat16 h2 = __float2bfloat16_rn(v.z);
    __nv_bfloat16 h3 = __float2bfloat16_rn(v.w);
    __nv_bfloat16 l0 = __float2bfloat16_rn(v.x - __bfloat162float(h0));
    __nv_bfloat16 l1 = __float2bfloat16_rn(v.y - __bfloat162float(h1));
    __nv_bfloat16 l2 = __float2bfloat16_rn(v.z - __bfloat162float(h2));
    __nv_bfloat16 l3 = __float2bfloat16_rn(v.w - __bfloat162float(h3));
    *(__nv_bfloat162*)(H + i)     = __halves2bfloat162(h0, h1);
    *(__nv_bfloat162*)(H + i + 2) = __halves2bfloat162(h2, h3);
    *(__nv_bfloat162*)(L + i)     = __halves2bfloat162(l0, l1);
    *(__nv_bfloat162*)(L + i + 2) = __halves2bfloat162(l2, l3);
}

// ===========================================================================
// transpose + split: W[K][N] fp32 -> HT/LT[N][K] bf16
// ===========================================================================
__global__ void splitT_bf16_kernel(const float* __restrict__ W,
                                   __nv_bfloat16* __restrict__ HT,
                                   __nv_bfloat16* __restrict__ LT)
{
    __shared__ float t[32][33];
    const int bx = blockIdx.x * 32;   // n
    const int by = blockIdx.y * 32;   // k
    const int x = threadIdx.x, y = threadIdx.y;   // 32 x 8
    #pragma unroll
    for (int j = 0; j < 32; j += 8)
        t[y + j][x] = W[(size_t)(by + y + j) * DM + bx + x];
    __syncthreads();
    #pragma unroll
    for (int j = 0; j < 32; j += 8) {
        float v = t[x][y + j];
        __nv_bfloat16 h = __float2bfloat16_rn(v);
        __nv_bfloat16 l = __float2bfloat16_rn(v - __bfloat162float(h));
        size_t o = (size_t)(bx + y + j) * DM + by + x;
        HT[o] = h;
        LT[o] = l;
    }
}

// ===========================================================================
// HMMA split-bf16 GEMM (unchanged from passing R8 kernel)
// ===========================================================================
#define SK 40

__global__ __launch_bounds__(256)
void hmma_gemm_kernel(const __nv_bfloat16* __restrict__ Ah,
                      const __nv_bfloat16* __restrict__ Al,
                      const __nv_bfloat16* __restrict__ BhT,
                      const __nv_bfloat16* __restrict__ BlT,
                      const float* __restrict__ bias,
                      float* __restrict__ C, int M, int N, int K)
{
    __shared__ __nv_bfloat16 sAh[128][SK], sAl[128][SK];
    __shared__ __nv_bfloat16 sBh[128][SK], sBl[128][SK];

    const int tid  = threadIdx.x;
    const int lane = tid & 31;
    const int wid  = tid >> 5;
    const int wm   = wid & 1;
    const int wn   = wid >> 1;
    const int row0 = blockIdx.y * 128;
    const int col0 = blockIdx.x * 128;

    float acc[4][4][4];
    #pragma unroll
    for (int i = 0; i < 4; ++i)
        #pragma unroll
        for (int j = 0; j < 4; ++j)
            #pragma unroll
            for (int k = 0; k < 4; ++k) acc[i][j][k] = 0.f;

    const int aRow = wm * 64 + ((lane >> 3) & 1) * 8 + (lane & 7);
    const int aK   = ((lane >> 4) & 1) * 8;
    const int bRow = wn * 32 + ((lane >> 4) & 1) * 8 + (lane & 7);
    const int bK   = ((lane >> 3) & 1) * 8;

    const uint32_t uAh = smem_to_u32(&sAh[aRow][aK]);
    const uint32_t uAl = smem_to_u32(&sAl[aRow][aK]);
    const uint32_t uBh = smem_to_u32(&sBh[bRow][bK]);
    const uint32_t uBl = smem_to_u32(&sBl[bRow][bK]);

    const __nv_bfloat16* gAh = Ah  + (size_t)row0 * K;
    const __nv_bfloat16* gAl = Al  + (size_t)row0 * K;
    const __nv_bfloat16* gBh = BhT + (size_t)col0 * K;
    const __nv_bfloat16* gBl = BlT + (size_t)col0 * K;

    const int lr  = tid >> 2;
    const int lc  = (tid & 3) * 8;

    for (int kc = 0; kc < K; kc += 32) {
        const size_t o1 = (size_t)lr * K + kc + lc;
        const size_t o2 = (size_t)(lr + 64) * K + kc + lc;
        *(uint4*)&sAh[lr][lc]      = *(const uint4*)(gAh + o1);
        *(uint4*)&sAh[lr + 64][lc] = *(const uint4*)(gAh + o2);
        *(uint4*)&sAl[lr][lc]      = *(const uint4*)(gAl + o1);
        *(uint4*)&sAl[lr + 64][lc] = *(const uint4*)(gAl + o2);
        *(uint4*)&sBh[lr][lc]      = *(const uint4*)(gBh + o1);
        *(uint4*)&sBh[lr + 64][lc] = *(const uint4*)(gBh + o2);
        *(uint4*)&sBl[lr][lc]      = *(const uint4*)(gBl + o1);
        *(uint4*)&sBl[lr + 64][lc] = *(const uint4*)(gBl + o2);
        __syncthreads();

        #pragma unroll
        for (int ks = 0; ks < 32; ks += 16) {
            uint32_t ahf[4][4], alf[4][4], bhf[2][4], blf[2][4];
            #pragma unroll
            for (int mt = 0; mt < 4; ++mt) {
                LDMX4(ahf[mt], uAh + mt * (16 * SK * 2) + ks * 2);
                LDMX4(alf[mt], uAl + mt * (16 * SK * 2) + ks * 2);
            }
            #pragma unroll
            for (int p = 0; p < 2; ++p) {
                LDMX4(bhf[p], uBh + p * (16 * SK * 2) + ks * 2);
                LDMX4(blf[p], uBl + p * (16 * SK * 2) + ks * 2);
            }
            #pragma unroll
            for (int mt = 0; mt < 4; ++mt) {
                #pragma unroll
                for (int nt = 0; nt < 4; ++nt) {
                    const uint32_t* bh2 = &bhf[nt >> 1][(nt & 1) * 2];
                    const uint32_t* bl2 = &blf[nt >> 1][(nt & 1) * 2];
                    mma_bf16(acc[mt][nt], ahf[mt], bh2[0], bh2[1]);
                    mma_bf16(acc[mt][nt], ahf[mt], bl2[0], bl2[1]);
                    mma_bf16(acc[mt][nt], alf[mt], bh2[0], bh2[1]);
                }
            }
        }
        __syncthreads();
    }

    #pragma unroll
    for (int mt = 0; mt < 4; ++mt) {
        const int r1 = row0 + wm * 64 + mt * 16 + (lane >> 2);
        const int r2 = r1 + 8;
        #pragma unroll
        for (int nt = 0; nt < 4; ++nt) {
            const int c = col0 + wn * 32 + nt * 8 + (lane & 3) * 2;
            const float b0 = bias[c], b1 = bias[c + 1];
            *(float2*)(C + (size_t)r1 * N + c) =
                make_float2(acc[mt][nt][0] + b0, acc[mt][nt][1] + b1);
            *(float2*)(C + (size_t)r2 * N + c) =
                make_float2(acc[mt][nt][2] + b0, acc[mt][nt][3] + b1);
        }
    }
}

// ===========================================================================
// HMMA flash attention with relative-position bias.
// Q tile 64 rows, 4 warps (16 rows each), KV tile 64.
// S = QhKh + QhKl + QlKh (split).  PE bias: QPE = Qh @ PEband^T (bf16, one
// pass), staged fp32 in smem, gathered as s_pe[i][j] = QPE[i][63+j-i].
// PV: P split hi/lo x V split hi/lo (3 passes).  fast_exp on fma pipe.
// ===========================================================================
#define ATT_SMEM (7 * 64 * 72 * 2 + 128 * 72 * 2 /*unused pad*/ )
// layout: Qh,Ql,Kh,Kl,Vh,Vl: 64x72 bf16 each; PE: 128x72 bf16; QPE: 64x136 f32
#define ATT_SMEM_BYTES (6 * 64 * 72 * 2 + 128 * 72 * 2 + 64 * 136 * 4)

__global__ __launch_bounds__(128)
void rel_attn_hmma_kernel(const float* __restrict__ Qg,
                          const float* __restrict__ Kg,
                          const float* __restrict__ Vg,
                          const float* __restrict__ PEg,
                          float* __restrict__ Og)
{
    extern __shared__ char smx[];
    __nv_bfloat16* sQh = (__nv_bfloat16*)smx;
    __nv_bfloat16* sQl = sQh + 64 * 72;
    __nv_bfloat16* sKh = sQl + 64 * 72;
    __nv_bfloat16* sKl = sKh + 64 * 72;
    __nv_bfloat16* sVh = sKl + 64 * 72;   // V^T: [d][j]
    __nv_bfloat16* sVl = sVh + 64 * 72;
    __nv_bfloat16* sPE = sVl + 64 * 72;   // [128][72] band rows
    float*         sQPE = (float*)(sPE + 128 * 72);  // [64][136]

    const int tid  = threadIdx.x;
    const int lane = tid & 31;
    const int w    = tid >> 5;
    const int qt   = (int)gridDim.x - 1 - (int)blockIdx.x;  // heavy first
    const int l0   = qt * 64;
    const int n    = blockIdx.y >> 4;
    const int h    = blockIdx.y & 15;

    // ---- load Q tile, split hi/lo ----
    const float* qbase = Qg + ((size_t)(n * LL + l0)) * DM + h * DH;
    for (int t = tid; t < 64 * 16; t += 128) {
        int r = t >> 4, c4 = (t & 15) << 2;
        float4 v = *(const float4*)(qbase + (size_t)r * DM + c4);
        __nv_bfloat16 hx = __float2bfloat16_rn(v.x);
        __nv_bfloat16 hy = __float2bfloat16_rn(v.y);
        __nv_bfloat16 hz = __float2bfloat16_rn(v.z);
        __nv_bfloat16 hw = __float2bfloat16_rn(v.w);
        *(__nv_bfloat162*)(sQh + r * 72 + c4)     = __halves2bfloat162(hx, hy);
        *(__nv_bfloat162*)(sQh + r * 72 + c4 + 2) = __halves2bfloat162(hz, hw);
        __nv_bfloat16 lx = __float2bfloat16_rn(v.x - __bfloat162float(hx));
        __nv_bfloat16 ly = __float2bfloat16_rn(v.y - __bfloat162float(hy));
        __nv_bfloat16 lz = __float2bfloat16_rn(v.z - __bfloat162float(hz));
        __nv_bfloat16 lw = __float2bfloat16_rn(v.w - __bfloat162float(hw));
        *(__nv_bfloat162*)(sQl + r * 72 + c4)     = __halves2bfloat162(lx, ly);
        *(__nv_bfloat162*)(sQl + r * 72 + c4 + 2) = __halves2bfloat162(lz, lw);
    }
    __syncthreads();

    // fragment addressing (R8-verified recipes)
    const int aRow = w * 16 + ((lane >> 3) & 1) * 8 + (lane & 7);
    const int aK   = ((lane >> 4) & 1) * 8;
    const int bRow = ((lane >> 4) & 1) * 8 + (lane & 7);
    const int bK   = ((lane >> 3) & 1) * 8;

    uint32_t qh[4][4], ql[4][4];
    {
        const uint32_t uQh = smem_to_u32(sQh + aRow * 72 + aK);
        const uint32_t uQl = smem_to_u32(sQl + aRow * 72 + aK);
        #pragma unroll
        for (int ks = 0; ks < 4; ++ks) {
            LDMX4(qh[ks], uQh + ks * 32);
            LDMX4(ql[ks], uQl + ks * 32);
        }
    }

    float o[8][4];
    #pragma unroll
    for (int i = 0; i < 8; ++i)
        #pragma unroll
        for (int j = 0; j < 4; ++j) o[i][j] = 0.f;
    float m0 = -1e30f, m1 = -1e30f, ls0acc = 0.f, ls1acc = 0.f;

    const int r0q = lane >> 2, c0 = (lane & 3) * 2;
    const int il0 = w * 16 + r0q, il1 = il0 + 8;
    const float* qpe0 = sQPE + il0 * 136 + 63 - il0;
    const float* qpe1 = sQPE + il1 * 136 + 63 - il1;
    float* qw0 = sQPE + il0 * 136 + c0;
    float* qw1 = sQPE + il1 * 136 + c0;

    for (int jt = 0; jt <= qt; ++jt) {
        const int j0 = jt * 64;
        const float* kb = Kg + ((size_t)(n * LL + j0)) * DM + h * DH;
        const float* vb = Vg + ((size_t)(n * LL + j0)) * DM + h * DH;

        // ---- K (direct) + V (transposed) loads with split ----
        for (int t = tid; t < 64 * 16; t += 128) {
            int r = t >> 4, c4 = (t & 15) << 2;
            float4 v = *(const float4*)(kb + (size_t)r * DM + c4);
            __nv_bfloat16 hx = __float2bfloat16_rn(v.x);
            __nv_bfloat16 hy = __float2bfloat16_rn(v.y);
            __nv_bfloat16 hz = __float2bfloat16_rn(v.z);
            __nv_bfloat16 hw = __float2bfloat16_rn(v.w);
            *(__nv_bfloat162*)(sKh + r * 72 + c4)     = __halves2bfloat162(hx, hy);
            *(__nv_bfloat162*)(sKh + r * 72 + c4 + 2) = __halves2bfloat162(hz, hw);
            __nv_bfloat16 lx = __float2bfloat16_rn(v.x - __bfloat162float(hx));
            __nv_bfloat16 ly = __float2bfloat16_rn(v.y - __bfloat162float(hy));
            __nv_bfloat16 lz = __float2bfloat16_rn(v.z - __bfloat162float(hz));
            __nv_bfloat16 lw = __float2bfloat16_rn(v.w - __bfloat162float(hw));
            *(__nv_bfloat162*)(sKl + r * 72 + c4)     = __halves2bfloat162(lx, ly);
            *(__nv_bfloat162*)(sKl + r * 72 + c4 + 2) = __halves2bfloat162(lz, lw);

            float4 u = *(const float4*)(vb + (size_t)r * DM + c4);
            float uv[4] = {u.x, u.y, u.z, u.w};
            #pragma unroll
            for (int e = 0; e < 4; ++e) {
                __nv_bfloat16 hh = __float2bfloat16_rn(uv[e]);
                sVh[(c4 + e) * 72 + r] = hh;
                sVl[(c4 + e) * 72 + r] =
                    __float2bfloat16_rn(uv[e] - __bfloat162float(hh));
            }
        }
        // ---- PE band rows (bf16 hi only) ----
        const int pebase = 1984 - l0 + j0;
        for (int t = tid; t < 128 * 16; t += 128) {
            int r = t >> 4, c4 = (t & 15) << 2;
            int gr = pebase + r;
            float4 v = make_float4(0.f, 0.f, 0.f, 0.f);
            if (gr < 2048) v = *(const float4*)(PEg + (size_t)gr * DH + c4);
            *(__nv_bfloat162*)(sPE + r * 72 + c4) =
                __halves2bfloat162(__float2bfloat16_rn(v.x),
                                   __float2bfloat16_rn(v.y));
            *(__nv_bfloat162*)(sPE + r * 72 + c4 + 2) =
                __halves2bfloat162(__float2bfloat16_rn(v.z),
                                   __float2bfloat16_rn(v.w));
        }
        __syncthreads();

        // ---- QPE = Qh @ PEband^T  (64 x 128, one bf16 pass) ----
        {
            float pacc[16][4];
            #pragma unroll
            for (int i = 0; i < 16; ++i)
                #pragma unroll
                for (int j = 0; j < 4; ++j) pacc[i][j] = 0.f;
            const uint32_t uPE = smem_to_u32(sPE + bRow * 72 + bK);
            #pragma unroll
            for (int ks = 0; ks < 4; ++ks) {
                uint32_t pf[8][4];
                #pragma unroll
                for (int p = 0; p < 8; ++p)
                    LDMX4(pf[p], uPE + p * (16 * 72 * 2) + ks * 32);
                #pragma unroll
                for (int nt = 0; nt < 16; ++nt)
                    mma_bf16(pacc[nt], qh[ks],
                             pf[nt >> 1][(nt & 1) * 2],
                             pf[nt >> 1][(nt & 1) * 2 + 1]);
            }
            #pragma unroll
            for (int nt = 0; nt < 16; ++nt) {
                qw0[nt * 8]     = pacc[nt][0];
                qw0[nt * 8 + 1] = pacc[nt][1];
                qw1[nt * 8]     = pacc[nt][2];
                qw1[nt * 8 + 1] = pacc[nt][3];
            }
            __syncwarp();
        }

        // ---- S = Q K^T (3-pass split) ----
        float s[8][4];
        #pragma unroll
        for (int i = 0; i < 8; ++i)
            #pragma unroll
            for (int j = 0; j < 4; ++j) s[i][j] = 0.f;
        {
            const uint32_t uKh = smem_to_u32(sKh + bRow * 72 + bK);
            const uint32_t uKl = smem_to_u32(sKl + bRow * 72 + bK);
            #pragma unroll
            for (int ks = 0; ks < 4; ++ks) {
                uint32_t kh[4][4], kl[4][4];
                #pragma unroll
                for (int p = 0; p < 4; ++p) {
                    LDMX4(kh[p], uKh + p * (16 * 72 * 2) + ks * 32);
                    LDMX4(kl[p], uKl + p * (16 * 72 * 2) + ks * 32);
                }
                #pragma unroll
                for (int nt = 0; nt < 8; ++nt) {
                    uint32_t b0h = kh[nt >> 1][(nt & 1) * 2];
                    uint32_t b1h = kh[nt >> 1][(nt & 1) * 2 + 1];
                    uint32_t b0l = kl[nt >> 1][(nt & 1) * 2];
                    uint32_t b1l = kl[nt >> 1][(nt & 1) * 2 + 1];
                    mma_bf16(s[nt], qh[ks], b0h, b1h);
                    mma_bf16(s[nt], qh[ks], b0l, b1l);
                    mma_bf16(s[nt], ql[ks], b0h, b1h);
                }
            }
        }

        // ---- bias + scale + mask + online softmax ----
        const bool bd = (jt == qt);
        float rmax0 = -1e30f, rmax1 = -1e30f;
        #pragma unroll
        for (int nt = 0; nt < 8; ++nt) {
            #pragma unroll
            for (int e = 0; e < 2; ++e) {
                const int jl = nt * 8 + c0 + e;
                float v0 = (s[nt][e] + qpe0[jl]) * 0.125f;
                if (bd && jl > il0) v0 = -1e9f;
                s[nt][e] = v0;
                rmax0 = fmaxf(rmax0, v0);
                float v1 = (s[nt][e + 2] + qpe1[jl]) * 0.125f;
                if (bd && jl > il1) v1 = -1e9f;
                s[nt][e + 2] = v1;
                rmax1 = fmaxf(rmax1, v1);
            }
        }
        rmax0 = fmaxf(rmax0, __shfl_xor_sync(0xffffffffu, rmax0, 1));
        rmax0 = fmaxf(rmax0, __shfl_xor_sync(0xffffffffu, rmax0, 2));
        rmax1 = fmaxf(rmax1, __shfl_xor_sync(0xffffffffu, rmax1, 1));
        rmax1 = fmaxf(rmax1, __shfl_xor_sync(0xffffffffu, rmax1, 2));

        const float mn0 = fmaxf(m0, rmax0), mn1 = fmaxf(m1, rmax1);
        const float a0 = fast_exp(m0 - mn0), a1 = fast_exp(m1 - mn1);
        m0 = mn0; m1 = mn1;

        float ls0 = 0.f, ls1 = 0.f;
        uint32_t pah[4][4], pal[4][4];
        #pragma unroll
        for (int nt = 0; nt < 8; ++nt) {
            float p0 = fast_exp(s[nt][0] - m0);
            float p1 = fast_exp(s[nt][1] - m0);
            float p2 = fast_exp(s[nt][2] - m1);
            float p3 = fast_exp(s[nt][3] - m1);
            ls0 += p0 + p1; ls1 += p2 + p3;
            __nv_bfloat16 h0 = __float2bfloat16_rn(p0);
            __nv_bfloat16 h1 = __float2bfloat16_rn(p1);
            __nv_bfloat16 h2 = __float2bfloat16_rn(p2);
            __nv_bfloat16 h3 = __float2bfloat16_rn(p3);
            __nv_bfloat162 t01 = __halves2bfloat162(h0, h1);
            __nv_bfloat162 t23 = __halves2bfloat162(h2, h3);
            const int kt = nt >> 1, off = (nt & 1) * 2;
            pah[kt][off]     = *reinterpret_cast<uint32_t*>(&t01);
            pah[kt][off + 1] = *reinterpret_cast<uint32_t*>(&t23);
            pal[kt][off]     = pack_bf2(p0 - __bfloat162float(h0),
                                        p1 - __bfloat162float(h1));
            pal[kt][off + 1] = pack_bf2(p2 - __bfloat162float(h2),
                                        p3 - __bfloat162float(h3));
        }
        ls0acc = ls0acc * a0 + ls0;
        ls1acc = ls1acc * a1 + ls1;
        #pragma unroll
        for (int nt = 0; nt < 8; ++nt) {
            o[nt][0] *= a0; o[nt][1] *= a0;
            o[nt][2] *= a1; o[nt][3] *= a1;
        }

        // ---- O += P V (3-pass split) ----
        {
            const uint32_t uVh = smem_to_u32(sVh + bRow * 72 + bK);
            const uint32_t uVl = smem_to_u32(sVl + bRow * 72 + bK);
            #pragma unroll
            for (int kt = 0; kt < 4; ++kt) {
                uint32_t vh[4][4], vl[4][4];
                #pragma unroll
                for (int p = 0; p < 4; ++p) {
                    LDMX4(vh[p], uVh + p * (16 * 72 * 2) + kt * 32);
                    LDMX4(vl[p], uVl + p * (16 * 72 * 2) + kt * 32);
                }
                #pragma unroll
                for (int dt = 0; dt < 8; ++dt) {
                    uint32_t b0h = vh[dt >> 1][(dt & 1) * 2];
                    uint32_t b1h = vh[dt >> 1][(dt & 1) * 2 + 1];
                    uint32_t b0l = vl[dt >> 1][(dt & 1) * 2];
                    uint32_t b1l = vl[dt >> 1][(dt & 1) * 2 + 1];
                    mma_bf16(o[dt], pah[kt], b0h, b1h);
                    mma_bf16(o[dt], pah[kt], b0l, b1l);
                    mma_bf16(o[dt], pal[kt], b0h, b1h);
                }
            }
        }
        __syncthreads();
    }

    // ---- epilogue: normalize + store ----
    float lt0 = ls0acc, lt1 = ls1acc;
    lt0 += __shfl_xor_sync(0xffffffffu, lt0, 1);
    lt0 += __shfl_xor_sync(0xffffffffu, lt0, 2);
    lt1 += __shfl_xor_sync(0xffffffffu, lt1, 1);
    lt1 += __shfl_xor_sync(0xffffffffu, lt1, 2);
    const float inv0 = 1.0f / lt0, inv1 = 1.0f / lt1;
    float* ob0 = Og + ((size_t)(n * LL + l0 + il0)) * DM + h * DH;
    float* ob1 = Og + ((size_t)(n * LL + l0 + il1)) * DM + h * DH;
    #pragma unroll
    for (int nt = 0; nt < 8; ++nt) {
        *(float2*)(ob0 + nt * 8 + c0) =
            make_float2(o[nt][0] * inv0, o[nt][1] * inv0);
        *(float2*)(ob1 + nt * 8 + c0) =
            make_float2(o[nt][2] * inv1, o[nt][3] * inv1);
    }
}

// ===========================================================================
extern "C" void kernel_launch(void* const* d_in, const int* in_sizes, int n_in,
                              void* d_out, int out_size)
{
    const float* q_in = (const float*)d_in[0];
    const float* k_in = (const float*)d_in[1];
    const float* v_in = (const float*)d_in[2];
    const float* Wq = (const float*)d_in[4];
    const float* bq = (const float*)d_in[5];
    const float* Wk = (const float*)d_in[6];
    const float* bk = (const float*)d_in[7];
    const float* Wv = (const float*)d_in[8];
    const float* bv = (const float*)d_in[9];
    const float* Wo = (const float*)d_in[10];
    const float* bo = (const float*)d_in[11];
    const float* pe = (const float*)d_in[12];
    float* out = (float*)d_out;

    float *Qp, *Kp, *Vp, *AOp;
    __nv_bfloat16 *Ahp, *Alp, *BhTp, *BlTp;
    cudaGetSymbolAddress((void**)&Qp,   g_Q);
    cudaGetSymbolAddress((void**)&Kp,   g_K);
    cudaGetSymbolAddress((void**)&Vp,   g_V);
    cudaGetSymbolAddress((void**)&AOp,  g_AO);
    cudaGetSymbolAddress((void**)&Ahp,  g_Ah);
    cudaGetSymbolAddress((void**)&Alp,  g_Al);
    cudaGetSymbolAddress((void**)&BhTp, g_BhT);
    cudaGetSymbolAddress((void**)&BlTp, g_BlT);

    cudaFuncSetAttribute(rel_attn_hmma_kernel,
                         cudaFuncAttributeMaxDynamicSharedMemorySize,
                         ATT_SMEM_BYTES);

    const int nA = MROWS * DM;
    const dim3 sp_grid(nA / 4 / 256);
    const dim3 tr_grid(DM / 32, DM / 32), tr_blk(32, 8);
    const dim3 mm_grid(DM / 128, MROWS / 128);

    split_bf16_kernel<<<sp_grid, 256>>>(q_in, Ahp, Alp, nA);
    splitT_bf16_kernel<<<tr_grid, tr_blk>>>(Wq, BhTp, BlTp);
    hmma_gemm_kernel<<<mm_grid, 256>>>(Ahp, Alp, BhTp, BlTp, bq, Qp,
                                       MROWS, DM, DM);

    split_bf16_kernel<<<sp_grid, 256>>>(k_in, Ahp, Alp, nA);
    splitT_bf16_kernel<<<tr_grid, tr_blk>>>(Wk, BhTp, BlTp);
    hmma_gemm_kernel<<<mm_grid, 256>>>(Ahp, Alp, BhTp, BlTp, bk, Kp,
                                       MROWS, DM, DM);

    split_bf16_kernel<<<sp_grid, 256>>>(v_in, Ahp, Alp, nA);
    splitT_bf16_kernel<<<tr_grid, tr_blk>>>(Wv, BhTp, BlTp);
    hmma_gemm_kernel<<<mm_grid, 256>>>(Ahp, Alp, BhTp, BlTp, bv, Vp,
                                       MROWS, DM, DM);

    rel_attn_hmma_kernel<<<dim3(LL / 64, NB * HH), 128, ATT_SMEM_BYTES>>>(
        Qp, Kp, Vp, pe, AOp);

    split_bf16_kernel<<<sp_grid, 256>>>(AOp, Ahp, Alp, nA);
    splitT_bf16_kernel<<<tr_grid, tr_blk>>>(Wo, BhTp, BlTp);
    hmma_gemm_kernel<<<mm_grid, 256>>>(Ahp, Alp, BhTp, BlTp, bo, out,
                                       MROWS, DM, DM);
}

// round 14
// speedup vs baseline: 2.6196x; 1.2626x over previous
#include <cuda_runtime.h>
#include <cuda_bf16.h>
#include <cstdint>

// Problem constants
#define DM     1024
#define NB     4
#define LL     1024
#define HH     16
#define DH     64
#define MROWS  (NB * LL)

typedef __nv_bfloat16 bf16;

// -------- scratch (allocation-free: __device__ globals) --------
__device__ bf16 g_Ah[MROWS * DM];    // GEMM A operand (hi)
__device__ bf16 g_Al[MROWS * DM];    // GEMM A operand (lo)
__device__ bf16 g_BhT[DM * DM];
__device__ bf16 g_BlT[DM * DM];
__device__ bf16 g_Qh[MROWS * DM], g_Ql[MROWS * DM];
__device__ bf16 g_Kh[MROWS * DM], g_Kl[MROWS * DM];
__device__ bf16 g_Vh[MROWS * DM], g_Vl[MROWS * DM];
__device__ bf16 g_VhT[MROWS * DM], g_VlT[MROWS * DM];   // [n][h][d][j]
__device__ bf16 g_AOh[MROWS * DM], g_AOl[MROWS * DM];
__device__ bf16 g_PEh[2048 * DH];

// =========================== helpers =======================================
__device__ __forceinline__ uint32_t smem_to_u32(const void* p) {
    uint32_t a;
    asm("{ .reg .u64 t; cvta.to.shared.u64 t, %1; cvt.u32.u64 %0, t; }"
        : "=r"(a) : "l"(p));
    return a;
}

#define LDMX4(r, addr)                                                        \
    asm volatile("ldmatrix.sync.aligned.m8n8.x4.shared.b16 "                  \
                 "{%0,%1,%2,%3}, [%4];"                                       \
                 : "=r"((r)[0]), "=r"((r)[1]), "=r"((r)[2]), "=r"((r)[3])     \
                 : "r"(addr))

__device__ __forceinline__ void mma_bf16(float* d, const uint32_t* a,
                                         uint32_t b0, uint32_t b1) {
    asm volatile(
        "mma.sync.aligned.m16n8k16.row.col.f32.bf16.bf16.f32 "
        "{%0,%1,%2,%3}, {%4,%5,%6,%7}, {%8,%9}, {%0,%1,%2,%3};"
        : "+f"(d[0]), "+f"(d[1]), "+f"(d[2]), "+f"(d[3])
        : "r"(a[0]), "r"(a[1]), "r"(a[2]), "r"(a[3]), "r"(b0), "r"(b1));
}

__device__ __forceinline__ void cpa16(uint32_t dst, const void* src) {
    asm volatile("cp.async.cg.shared.global [%0], [%1], 16;"
                 :: "r"(dst), "l"(src));
}
#define CP_COMMIT() asm volatile("cp.async.commit_group;")
#define CP_WAIT(n)  asm volatile("cp.async.wait_group %0;" :: "n"(n))

// fast exp on fma pipe (x <= 0)
__device__ __forceinline__ float fast_exp(float x) {
    float y = fmaxf(x * 1.44269504f, -126.0f);
    float r = rintf(y);
    float f = y - r;
    int   e = (int)r;
    float p = 1.33336e-3f;
    p = fmaf(p, f, 9.61812e-3f);
    p = fmaf(p, f, 5.55041e-2f);
    p = fmaf(p, f, 2.40226e-1f);
    p = fmaf(p, f, 6.93147e-1f);
    p = fmaf(p, f, 1.0f);
    return __int_as_float(__float_as_int(p) + (e << 23));
}

__device__ __forceinline__ uint32_t pack_bf2(float a, float b) {
    __nv_bfloat162 t = __halves2bfloat162(__float2bfloat16_rn(a),
                                          __float2bfloat16_rn(b));
    return *reinterpret_cast<uint32_t*>(&t);
}
__device__ __forceinline__ void split2(float v0, float v1,
                                       uint32_t& hi, uint32_t& lo) {
    bf16 h0 = __float2bfloat16_rn(v0), h1 = __float2bfloat16_rn(v1);
    __nv_bfloat162 th = __halves2bfloat162(h0, h1);
    hi = *reinterpret_cast<uint32_t*>(&th);
    lo = pack_bf2(v0 - __bfloat162float(h0), v1 - __bfloat162float(h1));
}

// ===========================================================================
// split fp32 -> (hi, lo) bf16, elementwise
// ===========================================================================
__global__ void split_bf16_kernel(const float* __restrict__ X,
                                  bf16* __restrict__ H,
                                  bf16* __restrict__ L, int n)
{
    int i = (blockIdx.x * blockDim.x + threadIdx.x) * 4;
    if (i >= n) return;
    float4 v = *(const float4*)(X + i);
    uint32_t h01, l01, h23, l23;
    split2(v.x, v.y, h01, l01);
    split2(v.z, v.w, h23, l23);
    *(uint32_t*)(H + i)     = h01;
    *(uint32_t*)(H + i + 2) = h23;
    *(uint32_t*)(L + i)     = l01;
    *(uint32_t*)(L + i + 2) = l23;
}

// ===========================================================================
// transpose + split: W[K][N] fp32 -> HT/LT[N][K] bf16
// ===========================================================================
__global__ void splitT_bf16_kernel(const float* __restrict__ W,
                                   bf16* __restrict__ HT,
                                   bf16* __restrict__ LT)
{
    __shared__ float t[32][33];
    const int bx = blockIdx.x * 32;
    const int by = blockIdx.y * 32;
    const int x = threadIdx.x, y = threadIdx.y;
    #pragma unroll
    for (int j = 0; j < 32; j += 8)
        t[y + j][x] = W[(size_t)(by + y + j) * DM + bx + x];
    __syncthreads();
    #pragma unroll
    for (int j = 0; j < 32; j += 8) {
        float v = t[x][y + j];
        bf16 h = __float2bfloat16_rn(v);
        bf16 l = __float2bfloat16_rn(v - __bfloat162float(h));
        size_t o = (size_t)(bx + y + j) * DM + by + x;
        HT[o] = h;
        LT[o] = l;
    }
}

// ===========================================================================
// bf16 per-head transpose: Vh/Vl [ (n*LL+j)*DM + h*DH+d ] ->
//                          VhT/VlT [ ((n*HH+h)*DH+d)*LL + j ]
// ===========================================================================
__global__ void vtrans_kernel(const bf16* __restrict__ Vh,
                              const bf16* __restrict__ Vl,
                              bf16* __restrict__ VhT,
                              bf16* __restrict__ VlT)
{
    __shared__ bf16 th[32][34], tl[32][34];
    const int nh = blockIdx.z;
    const int n = nh >> 4, h = nh & 15;
    const int j0 = blockIdx.x * 32, d0 = blockIdx.y * 32;
    const int x = threadIdx.x, y = threadIdx.y;   // 32 x 8
    #pragma unroll
    for (int jj = 0; jj < 32; jj += 8) {
        size_t src = (size_t)(n * LL + j0 + y + jj) * DM + h * DH + d0 + x;
        th[y + jj][x] = Vh[src];
        tl[y + jj][x] = Vl[src];
    }
    __syncthreads();
    #pragma unroll
    for (int jj = 0; jj < 32; jj += 8) {
        size_t dst = (size_t)((n * HH + h) * DH + d0 + y + jj) * LL + j0 + x;
        VhT[dst] = th[x][y + jj];
        VlT[dst] = tl[x][y + jj];
    }
}

// ===========================================================================
// PE -> bf16 (hi only)
// ===========================================================================
__global__ void pe_split_kernel(const float* __restrict__ PE,
                                bf16* __restrict__ PEh)
{
    int i = (blockIdx.x * blockDim.x + threadIdx.x) * 4;
    if (i >= 2048 * DH) return;
    float4 v = *(const float4*)(PE + i);
    *(uint32_t*)(PEh + i)     = pack_bf2(v.x, v.y);
    *(uint32_t*)(PEh + i + 2) = pack_bf2(v.z, v.w);
}

// ===========================================================================
// HMMA split-bf16 GEMM with cp.async 2-stage double buffering.
// C = A @ W + bias via AhBh + AhBl + AlBh.
// 128x128 block, 8 warps, warp tile 64x32, K-chunk 32.
// SPLIT_OUT=1: write (hi,lo) bf16 to Ch/Cl instead of fp32 C.
// ===========================================================================
#define SK 40
#define STG_BYTES (128 * SK * 2)            // 10240 per array
#define GEMM_SMEM (2 * 4 * STG_BYTES)       // 81920

template <int SPLIT_OUT>
__global__ __launch_bounds__(256)
void hmma_gemm_kernel(const bf16* __restrict__ Ah, const bf16* __restrict__ Al,
                      const bf16* __restrict__ BhT, const bf16* __restrict__ BlT,
                      const float* __restrict__ bias,
                      float* __restrict__ C,
                      bf16* __restrict__ Ch, bf16* __restrict__ Cl,
                      int M, int N, int K)
{
    extern __shared__ char gsm[];
    const uint32_t smem0 = smem_to_u32(gsm);

    const int tid  = threadIdx.x;
    const int lane = tid & 31;
    const int wid  = tid >> 5;
    const int wm   = wid & 1;
    const int wn   = wid >> 1;
    const int row0 = blockIdx.y * 128;
    const int col0 = blockIdx.x * 128;

    float acc[4][4][4];
    #pragma unroll
    for (int i = 0; i < 4; ++i)
        #pragma unroll
        for (int j = 0; j < 4; ++j)
            #pragma unroll
            for (int k = 0; k < 4; ++k) acc[i][j][k] = 0.f;

    const int aRow = wm * 64 + ((lane >> 3) & 1) * 8 + (lane & 7);
    const int aK   = ((lane >> 4) & 1) * 8;
    const int bRow = wn * 32 + ((lane >> 4) & 1) * 8 + (lane & 7);
    const int bK   = ((lane >> 3) & 1) * 8;
    const uint32_t laneA = (uint32_t)(aRow * SK + aK) * 2;
    const uint32_t laneB = (uint32_t)(bRow * SK + bK) * 2;

    const bf16* srcs[4] = { Ah + (size_t)row0 * K, Al + (size_t)row0 * K,
                            BhT + (size_t)col0 * K, BlT + (size_t)col0 * K };

    const int lr = tid >> 2;             // 0..63
    const int lc = (tid & 3) * 8;        // 0,8,16,24

    // prefetch stage 0
    {
        const uint32_t base = smem0;
        #pragma unroll
        for (int a = 0; a < 4; ++a) {
            const bf16* src = srcs[a];
            uint32_t d0 = base + a * STG_BYTES + lr * (SK * 2) + lc * 2;
            cpa16(d0, src + (size_t)lr * K + lc);
            cpa16(d0 + 64 * (SK * 2), src + (size_t)(lr + 64) * K + lc);
        }
        CP_COMMIT();
    }

    const int nIter = K / 32;
    for (int it = 0; it < nIter; ++it) {
        const int s = it & 1;
        if (it + 1 < nIter) {
            const int kc = (it + 1) * 32;
            const uint32_t base = smem0 + (s ^ 1) * (4 * STG_BYTES);
            #pragma unroll
            for (int a = 0; a < 4; ++a) {
                const bf16* src = srcs[a] + kc;
                uint32_t d0 = base + a * STG_BYTES + lr * (SK * 2) + lc * 2;
                cpa16(d0, src + (size_t)lr * K + lc);
                cpa16(d0 + 64 * (SK * 2), src + (size_t)(lr + 64) * K + lc);
            }
            CP_COMMIT();
            CP_WAIT(1);
        } else {
            CP_WAIT(0);
        }
        __syncthreads();

        const uint32_t base = smem0 + s * (4 * STG_BYTES);
        const uint32_t uAh = base + laneA;
        const uint32_t uAl = base + STG_BYTES + laneA;
        const uint32_t uBh = base + 2 * STG_BYTES + laneB;
        const uint32_t uBl = base + 3 * STG_BYTES + laneB;

        #pragma unroll
        for (int ks = 0; ks < 32; ks += 16) {
            uint32_t ahf[4][4], alf[4][4], bhf[2][4], blf[2][4];
            #pragma unroll
            for (int mt = 0; mt < 4; ++mt) {
                LDMX4(ahf[mt], uAh + mt * (16 * SK * 2) + ks * 2);
                LDMX4(alf[mt], uAl + mt * (16 * SK * 2) + ks * 2);
            }
            #pragma unroll
            for (int p = 0; p < 2; ++p) {
                LDMX4(bhf[p], uBh + p * (16 * SK * 2) + ks * 2);
                LDMX4(blf[p], uBl + p * (16 * SK * 2) + ks * 2);
            }
            #pragma unroll
            for (int mt = 0; mt < 4; ++mt) {
                #pragma unroll
                for (int nt = 0; nt < 4; ++nt) {
                    const uint32_t* bh2 = &bhf[nt >> 1][(nt & 1) * 2];
                    const uint32_t* bl2 = &blf[nt >> 1][(nt & 1) * 2];
                    mma_bf16(acc[mt][nt], ahf[mt], bh2[0], bh2[1]);
                    mma_bf16(acc[mt][nt], ahf[mt], bl2[0], bl2[1]);
                    mma_bf16(acc[mt][nt], alf[mt], bh2[0], bh2[1]);
                }
            }
        }
        __syncthreads();
    }

    #pragma unroll
    for (int mt = 0; mt < 4; ++mt) {
        const int r1 = row0 + wm * 64 + mt * 16 + (lane >> 2);
        const int r2 = r1 + 8;
        #pragma unroll
        for (int nt = 0; nt < 4; ++nt) {
            const int c = col0 + wn * 32 + nt * 8 + (lane & 3) * 2;
            const float b0 = bias[c], b1 = bias[c + 1];
            const float v0 = acc[mt][nt][0] + b0, v1 = acc[mt][nt][1] + b1;
            const float v2 = acc[mt][nt][2] + b0, v3 = acc[mt][nt][3] + b1;
            if (SPLIT_OUT) {
                uint32_t hi, lo;
                split2(v0, v1, hi, lo);
                *(uint32_t*)(Ch + (size_t)r1 * N + c) = hi;
                *(uint32_t*)(Cl + (size_t)r1 * N + c) = lo;
                split2(v2, v3, hi, lo);
                *(uint32_t*)(Ch + (size_t)r2 * N + c) = hi;
                *(uint32_t*)(Cl + (size_t)r2 * N + c) = lo;
            } else {
                *(float2*)(C + (size_t)r1 * N + c) = make_float2(v0, v1);
                *(float2*)(C + (size_t)r2 * N + c) = make_float2(v2, v3);
            }
        }
    }
}

// ===========================================================================
// HMMA flash attention with relative-position bias.
// All operands pre-split bf16; fills are pure vectorized copies.
// ===========================================================================
#define ATT_SMEM_BYTES (6 * 64 * 72 * 2 + 128 * 72 * 2 + 64 * 136 * 4)

__global__ __launch_bounds__(128)
void rel_attn_hmma_kernel(const bf16* __restrict__ Qhg,
                          const bf16* __restrict__ Qlg,
                          const bf16* __restrict__ Khg,
                          const bf16* __restrict__ Klg,
                          const bf16* __restrict__ VhTg,
                          const bf16* __restrict__ VlTg,
                          const bf16* __restrict__ PEhg,
                          bf16* __restrict__ AOh,
                          bf16* __restrict__ AOl)
{
    extern __shared__ char smx[];
    bf16* sQh = (bf16*)smx;
    bf16* sQl = sQh + 64 * 72;
    bf16* sKh = sQl + 64 * 72;
    bf16* sKl = sKh + 64 * 72;
    bf16* sVh = sKl + 64 * 72;   // V^T: [d][j]
    bf16* sVl = sVh + 64 * 72;
    bf16* sPE = sVl + 64 * 72;   // [128][72]
    float* sQPE = (float*)(sPE + 128 * 72);  // [64][136]

    const int tid  = threadIdx.x;
    const int lane = tid & 31;
    const int w    = tid >> 5;
    const int qt   = (int)gridDim.x - 1 - (int)blockIdx.x;
    const int l0   = qt * 64;
    const int n    = blockIdx.y >> 4;
    const int h    = blockIdx.y & 15;

    // ---- Q tile fill (bf16 copies) ----
    {
        const bf16* qh = Qhg + ((size_t)(n * LL + l0)) * DM + h * DH;
        const bf16* ql = Qlg + ((size_t)(n * LL + l0)) * DM + h * DH;
        for (int t = tid; t < 64 * 8; t += 128) {
            int r = t >> 3, c8 = (t & 7) * 8;
            *(uint4*)(sQh + r * 72 + c8) = *(const uint4*)(qh + (size_t)r * DM + c8);
            *(uint4*)(sQl + r * 72 + c8) = *(const uint4*)(ql + (size_t)r * DM + c8);
        }
    }
    __syncthreads();

    const int aRow = w * 16 + ((lane >> 3) & 1) * 8 + (lane & 7);
    const int aK   = ((lane >> 4) & 1) * 8;
    const int bRow = ((lane >> 4) & 1) * 8 + (lane & 7);
    const int bK   = ((lane >> 3) & 1) * 8;

    uint32_t qh[4][4], ql[4][4];
    {
        const uint32_t uQh = smem_to_u32(sQh + aRow * 72 + aK);
        const uint32_t uQl = smem_to_u32(sQl + aRow * 72 + aK);
        #pragma unroll
        for (int ks = 0; ks < 4; ++ks) {
            LDMX4(qh[ks], uQh + ks * 32);
            LDMX4(ql[ks], uQl + ks * 32);
        }
    }

    float o[8][4];
    #pragma unroll
    for (int i = 0; i < 8; ++i)
        #pragma unroll
        for (int j = 0; j < 4; ++j) o[i][j] = 0.f;
    float m0 = -1e30f, m1 = -1e30f, ls0acc = 0.f, ls1acc = 0.f;

    const int r0q = lane >> 2, c0 = (lane & 3) * 2;
    const int il0 = w * 16 + r0q, il1 = il0 + 8;
    const float* qpe0 = sQPE + il0 * 136 + 63 - il0;
    const float* qpe1 = sQPE + il1 * 136 + 63 - il1;
    float* qw0 = sQPE + il0 * 136 + c0;
    float* qw1 = sQPE + il1 * 136 + c0;

    for (int jt = 0; jt <= qt; ++jt) {
        const int j0 = jt * 64;

        // ---- K / V^T / PE fills: vectorized bf16 copies ----
        {
            const bf16* kh = Khg + ((size_t)(n * LL + j0)) * DM + h * DH;
            const bf16* kl = Klg + ((size_t)(n * LL + j0)) * DM + h * DH;
            const bf16* vh = VhTg + ((size_t)((n * HH + h) * DH)) * LL + j0;
            const bf16* vl = VlTg + ((size_t)((n * HH + h) * DH)) * LL + j0;
            for (int t = tid; t < 64 * 8; t += 128) {
                int r = t >> 3, c8 = (t & 7) * 8;
                *(uint4*)(sKh + r * 72 + c8) = *(const uint4*)(kh + (size_t)r * DM + c8);
                *(uint4*)(sKl + r * 72 + c8) = *(const uint4*)(kl + (size_t)r * DM + c8);
                *(uint4*)(sVh + r * 72 + c8) = *(const uint4*)(vh + (size_t)r * LL + c8);
                *(uint4*)(sVl + r * 72 + c8) = *(const uint4*)(vl + (size_t)r * LL + c8);
            }
            const int pebase = 1984 - l0 + j0;
            for (int t = tid; t < 128 * 8; t += 128) {
                int r = t >> 3, c8 = (t & 7) * 8;
                int gr = pebase + r;
                uint4 v = make_uint4(0u, 0u, 0u, 0u);
                if (gr < 2048) v = *(const uint4*)(PEhg + (size_t)gr * DH + c8);
                *(uint4*)(sPE + r * 72 + c8) = v;
            }
        }
        __syncthreads();

        // ---- QPE = Qh @ PEband^T ----
        {
            float pacc[16][4];
            #pragma unroll
            for (int i = 0; i < 16; ++i)
                #pragma unroll
                for (int j = 0; j < 4; ++j) pacc[i][j] = 0.f;
            const uint32_t uPE = smem_to_u32(sPE + bRow * 72 + bK);
            #pragma unroll
            for (int ks = 0; ks < 4; ++ks) {
                uint32_t pf[8][4];
                #pragma unroll
                for (int p = 0; p < 8; ++p)
                    LDMX4(pf[p], uPE + p * (16 * 72 * 2) + ks * 32);
                #pragma unroll
                for (int nt = 0; nt < 16; ++nt)
                    mma_bf16(pacc[nt], qh[ks],
                             pf[nt >> 1][(nt & 1) * 2],
                             pf[nt >> 1][(nt & 1) * 2 + 1]);
            }
            #pragma unroll
            for (int nt = 0; nt < 16; ++nt) {
                qw0[nt * 8]     = pacc[nt][0];
                qw0[nt * 8 + 1] = pacc[nt][1];
                qw1[nt * 8]     = pacc[nt][2];
                qw1[nt * 8 + 1] = pacc[nt][3];
            }
            __syncwarp();
        }

        // ---- S = Q K^T (3-pass split) ----
        float s[8][4];
        #pragma unroll
        for (int i = 0; i < 8; ++i)
            #pragma unroll
            for (int j = 0; j < 4; ++j) s[i][j] = 0.f;
        {
            const uint32_t uKh = smem_to_u32(sKh + bRow * 72 + bK);
            const uint32_t uKl = smem_to_u32(sKl + bRow * 72 + bK);
            #pragma unroll
            for (int ks = 0; ks < 4; ++ks) {
                uint32_t kh[4][4], kl[4][4];
                #pragma unroll
                for (int p = 0; p < 4; ++p) {
                    LDMX4(kh[p], uKh + p * (16 * 72 * 2) + ks * 32);
                    LDMX4(kl[p], uKl + p * (16 * 72 * 2) + ks * 32);
                }
                #pragma unroll
                for (int nt = 0; nt < 8; ++nt) {
                    uint32_t b0h = kh[nt >> 1][(nt & 1) * 2];
                    uint32_t b1h = kh[nt >> 1][(nt & 1) * 2 + 1];
                    uint32_t b0l = kl[nt >> 1][(nt & 1) * 2];
                    uint32_t b1l = kl[nt >> 1][(nt & 1) * 2 + 1];
                    mma_bf16(s[nt], qh[ks], b0h, b1h);
                    mma_bf16(s[nt], qh[ks], b0l, b1l);
                    mma_bf16(s[nt], ql[ks], b0h, b1h);
                }
            }
        }

        // ---- bias + scale + mask + online softmax ----
        const bool bd = (jt == qt);
        float rmax0 = -1e30f, rmax1 = -1e30f;
        #pragma unroll
        for (int nt = 0; nt < 8; ++nt) {
            #pragma unroll
            for (int e = 0; e < 2; ++e) {
                const int jl = nt * 8 + c0 + e;
                float v0 = (s[nt][e] + qpe0[jl]) * 0.125f;
                if (bd && jl > il0) v0 = -1e9f;
                s[nt][e] = v0;
                rmax0 = fmaxf(rmax0, v0);
                float v1 = (s[nt][e + 2] + qpe1[jl]) * 0.125f;
                if (bd && jl > il1) v1 = -1e9f;
                s[nt][e + 2] = v1;
                rmax1 = fmaxf(rmax1, v1);
            }
        }
        rmax0 = fmaxf(rmax0, __shfl_xor_sync(0xffffffffu, rmax0, 1));
        rmax0 = fmaxf(rmax0, __shfl_xor_sync(0xffffffffu, rmax0, 2));
        rmax1 = fmaxf(rmax1, __shfl_xor_sync(0xffffffffu, rmax1, 1));
        rmax1 = fmaxf(rmax1, __shfl_xor_sync(0xffffffffu, rmax1, 2));

        const float mn0 = fmaxf(m0, rmax0), mn1 = fmaxf(m1, rmax1);
        const float a0 = fast_exp(m0 - mn0), a1 = fast_exp(m1 - mn1);
        m0 = mn0; m1 = mn1;

        float ls0 = 0.f, ls1 = 0.f;
        uint32_t pah[4][4], pal[4][4];
        #pragma unroll
        for (int nt = 0; nt < 8; ++nt) {
            float p0 = fast_exp(s[nt][0] - m0);
            float p1 = fast_exp(s[nt][1] - m0);
            float p2 = fast_exp(s[nt][2] - m1);
            float p3 = fast_exp(s[nt][3] - m1);
            ls0 += p0 + p1; ls1 += p2 + p3;
            const int kt = nt >> 1, off = (nt & 1) * 2;
            uint32_t hi01, lo01, hi23, lo23;
            split2(p0, p1, hi01, lo01);
            split2(p2, p3, hi23, lo23);
            pah[kt][off]     = hi01;
            pah[kt][off + 1] = hi23;
            pal[kt][off]     = lo01;
            pal[kt][off + 1] = lo23;
        }
        ls0acc = ls0acc * a0 + ls0;
        ls1acc = ls1acc * a1 + ls1;
        #pragma unroll
        for (int nt = 0; nt < 8; ++nt) {
            o[nt][0] *= a0; o[nt][1] *= a0;
            o[nt][2] *= a1; o[nt][3] *= a1;
        }

        // ---- O += P V (3-pass split) ----
        {
            const uint32_t uVh = smem_to_u32(sVh + bRow * 72 + bK);
            const uint32_t uVl = smem_to_u32(sVl + bRow * 72 + bK);
            #pragma unroll
            for (int kt = 0; kt < 4; ++kt) {
                uint32_t vh[4][4], vl[4][4];
                #pragma unroll
                for (int p = 0; p < 4; ++p) {
                    LDMX4(vh[p], uVh + p * (16 * 72 * 2) + kt * 32);
                    LDMX4(vl[p], uVl + p * (16 * 72 * 2) + kt * 32);
                }
                #pragma unroll
                for (int dt = 0; dt < 8; ++dt) {
                    uint32_t b0h = vh[dt >> 1][(dt & 1) * 2];
                    uint32_t b1h = vh[dt >> 1][(dt & 1) * 2 + 1];
                    uint32_t b0l = vl[dt >> 1][(dt & 1) * 2];
                    uint32_t b1l = vl[dt >> 1][(dt & 1) * 2 + 1];
                    mma_bf16(o[dt], pah[kt], b0h, b1h);
                    mma_bf16(o[dt], pah[kt], b0l, b1l);
                    mma_bf16(o[dt], pal[kt], b0h, b1h);
                }
            }
        }
        __syncthreads();
    }

    // ---- epilogue: normalize + split-store for out-projection ----
    float lt0 = ls0acc, lt1 = ls1acc;
    lt0 += __shfl_xor_sync(0xffffffffu, lt0, 1);
    lt0 += __shfl_xor_sync(0xffffffffu, lt0, 2);
    lt1 += __shfl_xor_sync(0xffffffffu, lt1, 1);
    lt1 += __shfl_xor_sync(0xffffffffu, lt1, 2);
    const float inv0 = 1.0f / lt0, inv1 = 1.0f / lt1;
    bf16* oh0 = AOh + ((size_t)(n * LL + l0 + il0)) * DM + h * DH;
    bf16* ol0 = AOl + ((size_t)(n * LL + l0 + il0)) * DM + h * DH;
    bf16* oh1 = AOh + ((size_t)(n * LL + l0 + il1)) * DM + h * DH;
    bf16* ol1 = AOl + ((size_t)(n * LL + l0 + il1)) * DM + h * DH;
    #pragma unroll
    for (int nt = 0; nt < 8; ++nt) {
        uint32_t hi, lo;
        split2(o[nt][0] * inv0, o[nt][1] * inv0, hi, lo);
        *(uint32_t*)(oh0 + nt * 8 + c0) = hi;
        *(uint32_t*)(ol0 + nt * 8 + c0) = lo;
        split2(o[nt][2] * inv1, o[nt][3] * inv1, hi, lo);
        *(uint32_t*)(oh1 + nt * 8 + c0) = hi;
        *(uint32_t*)(ol1 + nt * 8 + c0) = lo;
    }
}

// ===========================================================================
extern "C" void kernel_launch(void* const* d_in, const int* in_sizes, int n_in,
                              void* d_out, int out_size)
{
    const float* q_in = (const float*)d_in[0];
    const float* k_in = (const float*)d_in[1];
    const float* v_in = (const float*)d_in[2];
    const float* Wq = (const float*)d_in[4];
    const float* bq = (const float*)d_in[5];
    const float* Wk = (const float*)d_in[6];
    const float* bk = (const float*)d_in[7];
    const float* Wv = (const float*)d_in[8];
    const float* bv = (const float*)d_in[9];
    const float* Wo = (const float*)d_in[10];
    const float* bo = (const float*)d_in[11];
    const float* pe = (const float*)d_in[12];
    float* out = (float*)d_out;

    bf16 *Ahp, *Alp, *BhTp, *BlTp, *Qhp, *Qlp, *Khp, *Klp;
    bf16 *Vhp, *Vlp, *VhTp, *VlTp, *AOhp, *AOlp, *PEhp;
    cudaGetSymbolAddress((void**)&Ahp,  g_Ah);
    cudaGetSymbolAddress((void**)&Alp,  g_Al);
    cudaGetSymbolAddress((void**)&BhTp, g_BhT);
    cudaGetSymbolAddress((void**)&BlTp, g_BlT);
    cudaGetSymbolAddress((void**)&Qhp,  g_Qh);
    cudaGetSymbolAddress((void**)&Qlp,  g_Ql);
    cudaGetSymbolAddress((void**)&Khp,  g_Kh);
    cudaGetSymbolAddress((void**)&Klp,  g_Kl);
    cudaGetSymbolAddress((void**)&Vhp,  g_Vh);
    cudaGetSymbolAddress((void**)&Vlp,  g_Vl);
    cudaGetSymbolAddress((void**)&VhTp, g_VhT);
    cudaGetSymbolAddress((void**)&VlTp, g_VlT);
    cudaGetSymbolAddress((void**)&AOhp, g_AOh);
    cudaGetSymbolAddress((void**)&AOlp, g_AOl);
    cudaGetSymbolAddress((void**)&PEhp, g_PEh);

    cudaFuncSetAttribute(rel_attn_hmma_kernel,
                         cudaFuncAttributeMaxDynamicSharedMemorySize,
                         ATT_SMEM_BYTES);
    cudaFuncSetAttribute(hmma_gemm_kernel<0>,
                         cudaFuncAttributeMaxDynamicSharedMemorySize,
                         GEMM_SMEM);
    cudaFuncSetAttribute(hmma_gemm_kernel<1>,
                         cudaFuncAttributeMaxDynamicSharedMemorySize,
                         GEMM_SMEM);

    const int nA = MROWS * DM;
    const dim3 sp_grid(nA / 4 / 256);
    const dim3 tr_grid(DM / 32, DM / 32), tr_blk(32, 8);
    const dim3 mm_grid(DM / 128, MROWS / 128);
    const dim3 vt_grid(LL / 32, DH / 32, NB * HH);

    pe_split_kernel<<<2048 * DH / 4 / 256, 256>>>(pe, PEhp);

    // Q = q_in @ Wq + bq  -> split bf16
    split_bf16_kernel<<<sp_grid, 256>>>(q_in, Ahp, Alp, nA);
    splitT_bf16_kernel<<<tr_grid, tr_blk>>>(Wq, BhTp, BlTp);
    hmma_gemm_kernel<1><<<mm_grid, 256, GEMM_SMEM>>>(
        Ahp, Alp, BhTp, BlTp, bq, nullptr, Qhp, Qlp, MROWS, DM, DM);

    // K
    split_bf16_kernel<<<sp_grid, 256>>>(k_in, Ahp, Alp, nA);
    splitT_bf16_kernel<<<tr_grid, tr_blk>>>(Wk, BhTp, BlTp);
    hmma_gemm_kernel<1><<<mm_grid, 256, GEMM_SMEM>>>(
        Ahp, Alp, BhTp, BlTp, bk, nullptr, Khp, Klp, MROWS, DM, DM);

    // V (+ per-head transpose)
    split_bf16_kernel<<<sp_grid, 256>>>(v_in, Ahp, Alp, nA);
    splitT_bf16_kernel<<<tr_grid, tr_blk>>>(Wv, BhTp, BlTp);
    hmma_gemm_kernel<1><<<mm_grid, 256, GEMM_SMEM>>>(
        Ahp, Alp, BhTp, BlTp, bv, nullptr, Vhp, Vlp, MROWS, DM, DM);
    vtrans_kernel<<<vt_grid, dim3(32, 8)>>>(Vhp, Vlp, VhTp, VlTp);

    // attention -> AOh/AOl (pre-split for out projection)
    rel_attn_hmma_kernel<<<dim3(LL / 64, NB * HH), 128, ATT_SMEM_BYTES>>>(
        Qhp, Qlp, Khp, Klp, VhTp, VlTp, PEhp, AOhp, AOlp);

    // out = AO @ Wo + bo (fp32 out)
    splitT_bf16_kernel<<<tr_grid, tr_blk>>>(Wo, BhTp, BlTp);
    hmma_gemm_kernel<0><<<mm_grid, 256, GEMM_SMEM>>>(
        AOhp, AOlp, BhTp, BlTp, bo, out, nullptr, nullptr, MROWS, DM, DM);
}

// round 15
// speedup vs baseline: 2.6283x; 1.0033x over previous
#include <cuda_runtime.h>
#include <cuda_bf16.h>
#include <cstdint>

// Problem constants
#define DM     1024
#define NB     4
#define LL     1024
#define HH     16
#define DH     64
#define MROWS  (NB * LL)
#define MA     ((size_t)MROWS * DM)     // per-z A/out stride
#define MB     ((size_t)DM * DM)        // per-z weight stride

typedef __nv_bfloat16 bf16;

// -------- scratch (allocation-free: __device__ globals) --------
__device__ bf16 g_Ah[3 * MROWS * DM];
__device__ bf16 g_Al[3 * MROWS * DM];
__device__ bf16 g_BhT[3 * DM * DM];
__device__ bf16 g_BlT[3 * DM * DM];
__device__ bf16 g_QKVh[3 * MROWS * DM];   // [Qh | Kh | Vh]
__device__ bf16 g_QKVl[3 * MROWS * DM];   // [Ql | Kl | Vl]
__device__ bf16 g_VhT[MROWS * DM], g_VlT[MROWS * DM];   // [n][h][d][j]
__device__ bf16 g_AOh[MROWS * DM], g_AOl[MROWS * DM];
__device__ bf16 g_PEh[2048 * DH];

// =========================== helpers =======================================
__device__ __forceinline__ uint32_t smem_to_u32(const void* p) {
    uint32_t a;
    asm("{ .reg .u64 t; cvta.to.shared.u64 t, %1; cvt.u32.u64 %0, t; }"
        : "=r"(a) : "l"(p));
    return a;
}

#define LDMX4(r, addr)                                                        \
    asm volatile("ldmatrix.sync.aligned.m8n8.x4.shared.b16 "                  \
                 "{%0,%1,%2,%3}, [%4];"                                       \
                 : "=r"((r)[0]), "=r"((r)[1]), "=r"((r)[2]), "=r"((r)[3])     \
                 : "r"(addr))

__device__ __forceinline__ void mma_bf16(float* d, const uint32_t* a,
                                         uint32_t b0, uint32_t b1) {
    asm volatile(
        "mma.sync.aligned.m16n8k16.row.col.f32.bf16.bf16.f32 "
        "{%0,%1,%2,%3}, {%4,%5,%6,%7}, {%8,%9}, {%0,%1,%2,%3};"
        : "+f"(d[0]), "+f"(d[1]), "+f"(d[2]), "+f"(d[3])
        : "r"(a[0]), "r"(a[1]), "r"(a[2]), "r"(a[3]), "r"(b0), "r"(b1));
}

__device__ __forceinline__ void cpa16(uint32_t dst, const void* src) {
    asm volatile("cp.async.cg.shared.global [%0], [%1], 16;"
                 :: "r"(dst), "l"(src));
}
#define CP_COMMIT() asm volatile("cp.async.commit_group;")
#define CP_WAIT(n)  asm volatile("cp.async.wait_group %0;" :: "n"(n))

// fast exp on fma pipe (x <= 0)
__device__ __forceinline__ float fast_exp(float x) {
    float y = fmaxf(x * 1.44269504f, -126.0f);
    float r = rintf(y);
    float f = y - r;
    int   e = (int)r;
    float p = 1.33336e-3f;
    p = fmaf(p, f, 9.61812e-3f);
    p = fmaf(p, f, 5.55041e-2f);
    p = fmaf(p, f, 2.40226e-1f);
    p = fmaf(p, f, 6.93147e-1f);
    p = fmaf(p, f, 1.0f);
    return __int_as_float(__float_as_int(p) + (e << 23));
}

__device__ __forceinline__ uint32_t pack_bf2(float a, float b) {
    __nv_bfloat162 t = __halves2bfloat162(__float2bfloat16_rn(a),
                                          __float2bfloat16_rn(b));
    return *reinterpret_cast<uint32_t*>(&t);
}
__device__ __forceinline__ void split2(float v0, float v1,
                                       uint32_t& hi, uint32_t& lo) {
    bf16 h0 = __float2bfloat16_rn(v0), h1 = __float2bfloat16_rn(v1);
    __nv_bfloat162 th = __halves2bfloat162(h0, h1);
    hi = *reinterpret_cast<uint32_t*>(&th);
    lo = pack_bf2(v0 - __bfloat162float(h0), v1 - __bfloat162float(h1));
}

// ===========================================================================
// fused split of 3 inputs: fp32 -> (hi, lo) bf16, z selects tensor
// ===========================================================================
__global__ void split3_kernel(const float* __restrict__ X0,
                              const float* __restrict__ X1,
                              const float* __restrict__ X2,
                              bf16* __restrict__ H, bf16* __restrict__ L,
                              int n)
{
    const int z = blockIdx.z;
    const float* X = (z == 0) ? X0 : (z == 1) ? X1 : X2;
    const size_t zo = (size_t)z * n;
    int i = (blockIdx.x * blockDim.x + threadIdx.x) * 4;
    if (i >= n) return;
    float4 v = *(const float4*)(X + i);
    uint32_t h01, l01, h23, l23;
    split2(v.x, v.y, h01, l01);
    split2(v.z, v.w, h23, l23);
    *(uint32_t*)(H + zo + i)     = h01;
    *(uint32_t*)(H + zo + i + 2) = h23;
    *(uint32_t*)(L + zo + i)     = l01;
    *(uint32_t*)(L + zo + i + 2) = l23;
}

// ===========================================================================
// fused transpose + split of up to 3 weights: W[K][N] -> HT/LT[N][K], z-sel
// ===========================================================================
__global__ void splitT3_kernel(const float* __restrict__ W0,
                               const float* __restrict__ W1,
                               const float* __restrict__ W2,
                               bf16* __restrict__ HT, bf16* __restrict__ LT)
{
    __shared__ float t[32][33];
    const int z = blockIdx.z;
    const float* W = (z == 0) ? W0 : (z == 1) ? W1 : W2;
    const size_t zo = (size_t)z * MB;
    const int bx = blockIdx.x * 32;
    const int by = blockIdx.y * 32;
    const int x = threadIdx.x, y = threadIdx.y;
    #pragma unroll
    for (int j = 0; j < 32; j += 8)
        t[y + j][x] = W[(size_t)(by + y + j) * DM + bx + x];
    __syncthreads();
    #pragma unroll
    for (int j = 0; j < 32; j += 8) {
        float v = t[x][y + j];
        bf16 h = __float2bfloat16_rn(v);
        bf16 l = __float2bfloat16_rn(v - __bfloat162float(h));
        size_t o = zo + (size_t)(bx + y + j) * DM + by + x;
        HT[o] = h;
        LT[o] = l;
    }
}

// ===========================================================================
// bf16 per-head transpose of V
// ===========================================================================
__global__ void vtrans_kernel(const bf16* __restrict__ Vh,
                              const bf16* __restrict__ Vl,
                              bf16* __restrict__ VhT,
                              bf16* __restrict__ VlT)
{
    __shared__ bf16 th[32][34], tl[32][34];
    const int nh = blockIdx.z;
    const int n = nh >> 4, h = nh & 15;
    const int j0 = blockIdx.x * 32, d0 = blockIdx.y * 32;
    const int x = threadIdx.x, y = threadIdx.y;   // 32 x 8
    #pragma unroll
    for (int jj = 0; jj < 32; jj += 8) {
        size_t src = (size_t)(n * LL + j0 + y + jj) * DM + h * DH + d0 + x;
        th[y + jj][x] = Vh[src];
        tl[y + jj][x] = Vl[src];
    }
    __syncthreads();
    #pragma unroll
    for (int jj = 0; jj < 32; jj += 8) {
        size_t dst = (size_t)((n * HH + h) * DH + d0 + y + jj) * LL + j0 + x;
        VhT[dst] = th[x][y + jj];
        VlT[dst] = tl[x][y + jj];
    }
}

// ===========================================================================
// PE -> bf16 (hi only)
// ===========================================================================
__global__ void pe_split_kernel(const float* __restrict__ PE,
                                bf16* __restrict__ PEh)
{
    int i = (blockIdx.x * blockDim.x + threadIdx.x) * 4;
    if (i >= 2048 * DH) return;
    float4 v = *(const float4*)(PE + i);
    *(uint32_t*)(PEh + i)     = pack_bf2(v.x, v.y);
    *(uint32_t*)(PEh + i + 2) = pack_bf2(v.z, v.w);
}

// ===========================================================================
// HMMA split-bf16 GEMM, cp.async double-buffered, one sync per iter,
// pass-major MMA ordering (no accumulator RAW chains).
// grid.z selects (A,B,bias,out) tuple; M=MROWS, N=K=DM fixed.
// ===========================================================================
#define SK 40
#define STG_BYTES (128 * SK * 2)            // 10240 per array
#define GEMM_SMEM (2 * 4 * STG_BYTES)       // 81920

template <int SPLIT_OUT>
__global__ __launch_bounds__(256)
void hmma_gemm_kernel(const bf16* __restrict__ Ahg, const bf16* __restrict__ Alg,
                      const bf16* __restrict__ BhTg, const bf16* __restrict__ BlTg,
                      const float* __restrict__ bias0,
                      const float* __restrict__ bias1,
                      const float* __restrict__ bias2,
                      float* __restrict__ C,
                      bf16* __restrict__ Chg, bf16* __restrict__ Clg)
{
    extern __shared__ char gsm[];
    const uint32_t smem0 = smem_to_u32(gsm);

    const int z = blockIdx.z;
    const float* bias = (z == 0) ? bias0 : (z == 1) ? bias1 : bias2;
    const bf16* Ah  = Ahg  + (size_t)z * MA;
    const bf16* Al  = Alg  + (size_t)z * MA;
    const bf16* BhT = BhTg + (size_t)z * MB;
    const bf16* BlT = BlTg + (size_t)z * MB;
    bf16* Ch = SPLIT_OUT ? (Chg + (size_t)z * MA) : nullptr;
    bf16* Cl = SPLIT_OUT ? (Clg + (size_t)z * MA) : nullptr;

    const int tid  = threadIdx.x;
    const int lane = tid & 31;
    const int wid  = tid >> 5;
    const int wm   = wid & 1;
    const int wn   = wid >> 1;
    const int row0 = blockIdx.y * 128;
    const int col0 = blockIdx.x * 128;

    float acc[4][4][4];
    #pragma unroll
    for (int i = 0; i < 4; ++i)
        #pragma unroll
        for (int j = 0; j < 4; ++j)
            #pragma unroll
            for (int k = 0; k < 4; ++k) acc[i][j][k] = 0.f;

    const int aRow = wm * 64 + ((lane >> 3) & 1) * 8 + (lane & 7);
    const int aK   = ((lane >> 4) & 1) * 8;
    const int bRow = wn * 32 + ((lane >> 4) & 1) * 8 + (lane & 7);
    const int bK   = ((lane >> 3) & 1) * 8;
    const uint32_t laneA = (uint32_t)(aRow * SK + aK) * 2;
    const uint32_t laneB = (uint32_t)(bRow * SK + bK) * 2;

    const bf16* srcs[4] = { Ah + (size_t)row0 * DM, Al + (size_t)row0 * DM,
                            BhT + (size_t)col0 * DM, BlT + (size_t)col0 * DM };

    const int lr = tid >> 2;             // 0..63
    const int lc = (tid & 3) * 8;        // 0,8,16,24

    // prefetch stage 0
    #pragma unroll
    for (int a = 0; a < 4; ++a) {
        const bf16* src = srcs[a];
        uint32_t d0 = smem0 + a * STG_BYTES + lr * (SK * 2) + lc * 2;
        cpa16(d0, src + (size_t)lr * DM + lc);
        cpa16(d0 + 64 * (SK * 2), src + (size_t)(lr + 64) * DM + lc);
    }
    CP_COMMIT();

    const int nIter = DM / 32;
    for (int it = 0; it < nIter; ++it) {
        const int s = it & 1;
        CP_WAIT(0);
        __syncthreads();
        if (it + 1 < nIter) {
            const int kc = (it + 1) * 32;
            const uint32_t base = smem0 + (s ^ 1) * (4 * STG_BYTES);
            #pragma unroll
            for (int a = 0; a < 4; ++a) {
                const bf16* src = srcs[a] + kc;
                uint32_t d0 = base + a * STG_BYTES + lr * (SK * 2) + lc * 2;
                cpa16(d0, src + (size_t)lr * DM + lc);
                cpa16(d0 + 64 * (SK * 2), src + (size_t)(lr + 64) * DM + lc);
            }
            CP_COMMIT();
        }

        const uint32_t base = smem0 + s * (4 * STG_BYTES);
        const uint32_t uAh = base + laneA;
        const uint32_t uAl = base + STG_BYTES + laneA;
        const uint32_t uBh = base + 2 * STG_BYTES + laneB;
        const uint32_t uBl = base + 3 * STG_BYTES + laneB;

        #pragma unroll
        for (int ks = 0; ks < 32; ks += 16) {
            uint32_t ahf[4][4], alf[4][4], bhf[2][4], blf[2][4];
            #pragma unroll
            for (int mt = 0; mt < 4; ++mt) {
                LDMX4(ahf[mt], uAh + mt * (16 * SK * 2) + ks * 2);
                LDMX4(alf[mt], uAl + mt * (16 * SK * 2) + ks * 2);
            }
            #pragma unroll
            for (int p = 0; p < 2; ++p) {
                LDMX4(bhf[p], uBh + p * (16 * SK * 2) + ks * 2);
                LDMX4(blf[p], uBl + p * (16 * SK * 2) + ks * 2);
            }
            // pass-major: 16 independent MMAs between same-acc reuses
            #pragma unroll
            for (int mt = 0; mt < 4; ++mt)
                #pragma unroll
                for (int nt = 0; nt < 4; ++nt)
                    mma_bf16(acc[mt][nt], ahf[mt],
                             bhf[nt >> 1][(nt & 1) * 2],
                             bhf[nt >> 1][(nt & 1) * 2 + 1]);
            #pragma unroll
            for (int mt = 0; mt < 4; ++mt)
                #pragma unroll
                for (int nt = 0; nt < 4; ++nt)
                    mma_bf16(acc[mt][nt], ahf[mt],
                             blf[nt >> 1][(nt & 1) * 2],
                             blf[nt >> 1][(nt & 1) * 2 + 1]);
            #pragma unroll
            for (int mt = 0; mt < 4; ++mt)
                #pragma unroll
                for (int nt = 0; nt < 4; ++nt)
                    mma_bf16(acc[mt][nt], alf[mt],
                             bhf[nt >> 1][(nt & 1) * 2],
                             bhf[nt >> 1][(nt & 1) * 2 + 1]);
        }
        __syncthreads();
    }

    #pragma unroll
    for (int mt = 0; mt < 4; ++mt) {
        const int r1 = row0 + wm * 64 + mt * 16 + (lane >> 2);
        const int r2 = r1 + 8;
        #pragma unroll
        for (int nt = 0; nt < 4; ++nt) {
            const int c = col0 + wn * 32 + nt * 8 + (lane & 3) * 2;
            const float b0 = bias[c], b1 = bias[c + 1];
            const float v0 = acc[mt][nt][0] + b0, v1 = acc[mt][nt][1] + b1;
            const float v2 = acc[mt][nt][2] + b0, v3 = acc[mt][nt][3] + b1;
            if (SPLIT_OUT) {
                uint32_t hi, lo;
                split2(v0, v1, hi, lo);
                *(uint32_t*)(Ch + (size_t)r1 * DM + c) = hi;
                *(uint32_t*)(Cl + (size_t)r1 * DM + c) = lo;
                split2(v2, v3, hi, lo);
                *(uint32_t*)(Ch + (size_t)r2 * DM + c) = hi;
                *(uint32_t*)(Cl + (size_t)r2 * DM + c) = lo;
            } else {
                *(float2*)(C + (size_t)r1 * DM + c) = make_float2(v0, v1);
                *(float2*)(C + (size_t)r2 * DM + c) = make_float2(v2, v3);
            }
        }
    }
}

// ===========================================================================
// HMMA flash attention with relative-position bias (pass-major MMA order).
// ===========================================================================
#define ATT_SMEM_BYTES (6 * 64 * 72 * 2 + 128 * 72 * 2 + 64 * 136 * 4)

__global__ __launch_bounds__(128)
void rel_attn_hmma_kernel(const bf16* __restrict__ Qhg,
                          const bf16* __restrict__ Qlg,
                          const bf16* __restrict__ Khg,
                          const bf16* __restrict__ Klg,
                          const bf16* __restrict__ VhTg,
                          const bf16* __restrict__ VlTg,
                          const bf16* __restrict__ PEhg,
                          bf16* __restrict__ AOh,
                          bf16* __restrict__ AOl)
{
    extern __shared__ char smx[];
    bf16* sQh = (bf16*)smx;
    bf16* sQl = sQh + 64 * 72;
    bf16* sKh = sQl + 64 * 72;
    bf16* sKl = sKh + 64 * 72;
    bf16* sVh = sKl + 64 * 72;   // V^T: [d][j]
    bf16* sVl = sVh + 64 * 72;
    bf16* sPE = sVl + 64 * 72;   // [128][72]
    float* sQPE = (float*)(sPE + 128 * 72);  // [64][136]

    const int tid  = threadIdx.x;
    const int lane = tid & 31;
    const int w    = tid >> 5;
    const int qt   = (int)gridDim.x - 1 - (int)blockIdx.x;
    const int l0   = qt * 64;
    const int n    = blockIdx.y >> 4;
    const int h    = blockIdx.y & 15;

    {
        const bf16* qh = Qhg + ((size_t)(n * LL + l0)) * DM + h * DH;
        const bf16* ql = Qlg + ((size_t)(n * LL + l0)) * DM + h * DH;
        for (int t = tid; t < 64 * 8; t += 128) {
            int r = t >> 3, c8 = (t & 7) * 8;
            *(uint4*)(sQh + r * 72 + c8) = *(const uint4*)(qh + (size_t)r * DM + c8);
            *(uint4*)(sQl + r * 72 + c8) = *(const uint4*)(ql + (size_t)r * DM + c8);
        }
    }
    __syncthreads();

    const int aRow = w * 16 + ((lane >> 3) & 1) * 8 + (lane & 7);
    const int aK   = ((lane >> 4) & 1) * 8;
    const int bRow = ((lane >> 4) & 1) * 8 + (lane & 7);
    const int bK   = ((lane >> 3) & 1) * 8;

    uint32_t qh[4][4], ql[4][4];
    {
        const uint32_t uQh = smem_to_u32(sQh + aRow * 72 + aK);
        const uint32_t uQl = smem_to_u32(sQl + aRow * 72 + aK);
        #pragma unroll
        for (int ks = 0; ks < 4; ++ks) {
            LDMX4(qh[ks], uQh + ks * 32);
            LDMX4(ql[ks], uQl + ks * 32);
        }
    }

    float o[8][4];
    #pragma unroll
    for (int i = 0; i < 8; ++i)
        #pragma unroll
        for (int j = 0; j < 4; ++j) o[i][j] = 0.f;
    float m0 = -1e30f, m1 = -1e30f, ls0acc = 0.f, ls1acc = 0.f;

    const int r0q = lane >> 2, c0 = (lane & 3) * 2;
    const int il0 = w * 16 + r0q, il1 = il0 + 8;
    const float* qpe0 = sQPE + il0 * 136 + 63 - il0;
    const float* qpe1 = sQPE + il1 * 136 + 63 - il1;
    float* qw0 = sQPE + il0 * 136 + c0;
    float* qw1 = sQPE + il1 * 136 + c0;

    for (int jt = 0; jt <= qt; ++jt) {
        const int j0 = jt * 64;

        {
            const bf16* kh = Khg + ((size_t)(n * LL + j0)) * DM + h * DH;
            const bf16* kl = Klg + ((size_t)(n * LL + j0)) * DM + h * DH;
            const bf16* vh = VhTg + ((size_t)((n * HH + h) * DH)) * LL + j0;
            const bf16* vl = VlTg + ((size_t)((n * HH + h) * DH)) * LL + j0;
            for (int t = tid; t < 64 * 8; t += 128) {
                int r = t >> 3, c8 = (t & 7) * 8;
                *(uint4*)(sKh + r * 72 + c8) = *(const uint4*)(kh + (size_t)r * DM + c8);
                *(uint4*)(sKl + r * 72 + c8) = *(const uint4*)(kl + (size_t)r * DM + c8);
                *(uint4*)(sVh + r * 72 + c8) = *(const uint4*)(vh + (size_t)r * LL + c8);
                *(uint4*)(sVl + r * 72 + c8) = *(const uint4*)(vl + (size_t)r * LL + c8);
            }
            const int pebase = 1984 - l0 + j0;
            for (int t = tid; t < 128 * 8; t += 128) {
                int r = t >> 3, c8 = (t & 7) * 8;
                int gr = pebase + r;
                uint4 v = make_uint4(0u, 0u, 0u, 0u);
                if (gr < 2048) v = *(const uint4*)(PEhg + (size_t)gr * DH + c8);
                *(uint4*)(sPE + r * 72 + c8) = v;
            }
        }
        __syncthreads();

        // ---- QPE = Qh @ PEband^T ----
        {
            float pacc[16][4];
            #pragma unroll
            for (int i = 0; i < 16; ++i)
                #pragma unroll
                for (int j = 0; j < 4; ++j) pacc[i][j] = 0.f;
            const uint32_t uPE = smem_to_u32(sPE + bRow * 72 + bK);
            #pragma unroll
            for (int ks = 0; ks < 4; ++ks) {
                uint32_t pf[8][4];
                #pragma unroll
                for (int p = 0; p < 8; ++p)
                    LDMX4(pf[p], uPE + p * (16 * 72 * 2) + ks * 32);
                #pragma unroll
                for (int nt = 0; nt < 16; ++nt)
                    mma_bf16(pacc[nt], qh[ks],
                             pf[nt >> 1][(nt & 1) * 2],
                             pf[nt >> 1][(nt & 1) * 2 + 1]);
            }
            #pragma unroll
            for (int nt = 0; nt < 16; ++nt) {
                qw0[nt * 8]     = pacc[nt][0];
                qw0[nt * 8 + 1] = pacc[nt][1];
                qw1[nt * 8]     = pacc[nt][2];
                qw1[nt * 8 + 1] = pacc[nt][3];
            }
            __syncwarp();
        }

        // ---- S = Q K^T (3 passes, pass-major) ----
        float s[8][4];
        #pragma unroll
        for (int i = 0; i < 8; ++i)
            #pragma unroll
            for (int j = 0; j < 4; ++j) s[i][j] = 0.f;
        {
            const uint32_t uKh = smem_to_u32(sKh + bRow * 72 + bK);
            const uint32_t uKl = smem_to_u32(sKl + bRow * 72 + bK);
            #pragma unroll
            for (int ks = 0; ks < 4; ++ks) {
                uint32_t kh[4][4], kl[4][4];
                #pragma unroll
                for (int p = 0; p < 4; ++p) {
                    LDMX4(kh[p], uKh + p * (16 * 72 * 2) + ks * 32);
                    LDMX4(kl[p], uKl + p * (16 * 72 * 2) + ks * 32);
                }
                #pragma unroll
                for (int nt = 0; nt < 8; ++nt)
                    mma_bf16(s[nt], qh[ks], kh[nt >> 1][(nt & 1) * 2],
                             kh[nt >> 1][(nt & 1) * 2 + 1]);
                #pragma unroll
                for (int nt = 0; nt < 8; ++nt)
                    mma_bf16(s[nt], qh[ks], kl[nt >> 1][(nt & 1) * 2],
                             kl[nt >> 1][(nt & 1) * 2 + 1]);
                #pragma unroll
                for (int nt = 0; nt < 8; ++nt)
                    mma_bf16(s[nt], ql[ks], kh[nt >> 1][(nt & 1) * 2],
                             kh[nt >> 1][(nt & 1) * 2 + 1]);
            }
        }

        // ---- bias + scale + mask + online softmax ----
        const bool bd = (jt == qt);
        float rmax0 = -1e30f, rmax1 = -1e30f;
        #pragma unroll
        for (int nt = 0; nt < 8; ++nt) {
            #pragma unroll
            for (int e = 0; e < 2; ++e) {
                const int jl = nt * 8 + c0 + e;
                float v0 = (s[nt][e] + qpe0[jl]) * 0.125f;
                if (bd && jl > il0) v0 = -1e9f;
                s[nt][e] = v0;
                rmax0 = fmaxf(rmax0, v0);
                float v1 = (s[nt][e + 2] + qpe1[jl]) * 0.125f;
                if (bd && jl > il1) v1 = -1e9f;
                s[nt][e + 2] = v1;
                rmax1 = fmaxf(rmax1, v1);
            }
        }
        rmax0 = fmaxf(rmax0, __shfl_xor_sync(0xffffffffu, rmax0, 1));
        rmax0 = fmaxf(rmax0, __shfl_xor_sync(0xffffffffu, rmax0, 2));
        rmax1 = fmaxf(rmax1, __shfl_xor_sync(0xffffffffu, rmax1, 1));
        rmax1 = fmaxf(rmax1, __shfl_xor_sync(0xffffffffu, rmax1, 2));

        const float mn0 = fmaxf(m0, rmax0), mn1 = fmaxf(m1, rmax1);
        const float a0 = fast_exp(m0 - mn0), a1 = fast_exp(m1 - mn1);
        m0 = mn0; m1 = mn1;

        float ls0 = 0.f, ls1 = 0.f;
        uint32_t pah[4][4], pal[4][4];
        #pragma unroll
        for (int nt = 0; nt < 8; ++nt) {
            float p0 = fast_exp(s[nt][0] - m0);
            float p1 = fast_exp(s[nt][1] - m0);
            float p2 = fast_exp(s[nt][2] - m1);
            float p3 = fast_exp(s[nt][3] - m1);
            ls0 += p0 + p1; ls1 += p2 + p3;
            const int kt = nt >> 1, off = (nt & 1) * 2;
            uint32_t hi01, lo01, hi23, lo23;
            split2(p0, p1, hi01, lo01);
            split2(p2, p3, hi23, lo23);
            pah[kt][off]     = hi01;
            pah[kt][off + 1] = hi23;
            pal[kt][off]     = lo01;
            pal[kt][off + 1] = lo23;
        }
        ls0acc = ls0acc * a0 + ls0;
        ls1acc = ls1acc * a1 + ls1;
        #pragma unroll
        for (int nt = 0; nt < 8; ++nt) {
            o[nt][0] *= a0; o[nt][1] *= a0;
            o[nt][2] *= a1; o[nt][3] *= a1;
        }

        // ---- O += P V (3 passes, pass-major) ----
        {
            const uint32_t uVh = smem_to_u32(sVh + bRow * 72 + bK);
            const uint32_t uVl = smem_to_u32(sVl + bRow * 72 + bK);
            #pragma unroll
            for (int kt = 0; kt < 4; ++kt) {
                uint32_t vh[4][4], vl[4][4];
                #pragma unroll
                for (int p = 0; p < 4; ++p) {
                    LDMX4(vh[p], uVh + p * (16 * 72 * 2) + kt * 32);
                    LDMX4(vl[p], uVl + p * (16 * 72 * 2) + kt * 32);
                }
                #pragma unroll
                for (int dt = 0; dt < 8; ++dt)
                    mma_bf16(o[dt], pah[kt], vh[dt >> 1][(dt & 1) * 2],
                             vh[dt >> 1][(dt & 1) * 2 + 1]);
                #pragma unroll
                for (int dt = 0; dt < 8; ++dt)
                    mma_bf16(o[dt], pah[kt], vl[dt >> 1][(dt & 1) * 2],
                             vl[dt >> 1][(dt & 1) * 2 + 1]);
                #pragma unroll
                for (int dt = 0; dt < 8; ++dt)
                    mma_bf16(o[dt], pal[kt], vh[dt >> 1][(dt & 1) * 2],
                             vh[dt >> 1][(dt & 1) * 2 + 1]);
            }
        }
        __syncthreads();
    }

    // ---- epilogue ----
    float lt0 = ls0acc, lt1 = ls1acc;
    lt0 += __shfl_xor_sync(0xffffffffu, lt0, 1);
    lt0 += __shfl_xor_sync(0xffffffffu, lt0, 2);
    lt1 += __shfl_xor_sync(0xffffffffu, lt1, 1);
    lt1 += __shfl_xor_sync(0xffffffffu, lt1, 2);
    const float inv0 = 1.0f / lt0, inv1 = 1.0f / lt1;
    bf16* oh0 = AOh + ((size_t)(n * LL + l0 + il0)) * DM + h * DH;
    bf16* ol0 = AOl + ((size_t)(n * LL + l0 + il0)) * DM + h * DH;
    bf16* oh1 = AOh + ((size_t)(n * LL + l0 + il1)) * DM + h * DH;
    bf16* ol1 = AOl + ((size_t)(n * LL + l0 + il1)) * DM + h * DH;
    #pragma unroll
    for (int nt = 0; nt < 8; ++nt) {
        uint32_t hi, lo;
        split2(o[nt][0] * inv0, o[nt][1] * inv0, hi, lo);
        *(uint32_t*)(oh0 + nt * 8 + c0) = hi;
        *(uint32_t*)(ol0 + nt * 8 + c0) = lo;
        split2(o[nt][2] * inv1, o[nt][3] * inv1, hi, lo);
        *(uint32_t*)(oh1 + nt * 8 + c0) = hi;
        *(uint32_t*)(ol1 + nt * 8 + c0) = lo;
    }
}

// ===========================================================================
extern "C" void kernel_launch(void* const* d_in, const int* in_sizes, int n_in,
                              void* d_out, int out_size)
{
    const float* q_in = (const float*)d_in[0];
    const float* k_in = (const float*)d_in[1];
    const float* v_in = (const float*)d_in[2];
    const float* Wq = (const float*)d_in[4];
    const float* bq = (const float*)d_in[5];
    const float* Wk = (const float*)d_in[6];
    const float* bk = (const float*)d_in[7];
    const float* Wv = (const float*)d_in[8];
    const float* bv = (const float*)d_in[9];
    const float* Wo = (const float*)d_in[10];
    const float* bo = (const float*)d_in[11];
    const float* pe = (const float*)d_in[12];
    float* out = (float*)d_out;

    bf16 *Ahp, *Alp, *BhTp, *BlTp, *QKVhp, *QKVlp;
    bf16 *VhTp, *VlTp, *AOhp, *AOlp, *PEhp;
    cudaGetSymbolAddress((void**)&Ahp,   g_Ah);
    cudaGetSymbolAddress((void**)&Alp,   g_Al);
    cudaGetSymbolAddress((void**)&BhTp,  g_BhT);
    cudaGetSymbolAddress((void**)&BlTp,  g_BlT);
    cudaGetSymbolAddress((void**)&QKVhp, g_QKVh);
    cudaGetSymbolAddress((void**)&QKVlp, g_QKVl);
    cudaGetSymbolAddress((void**)&VhTp,  g_VhT);
    cudaGetSymbolAddress((void**)&VlTp,  g_VlT);
    cudaGetSymbolAddress((void**)&AOhp,  g_AOh);
    cudaGetSymbolAddress((void**)&AOlp,  g_AOl);
    cudaGetSymbolAddress((void**)&PEhp,  g_PEh);

    cudaFuncSetAttribute(rel_attn_hmma_kernel,
                         cudaFuncAttributeMaxDynamicSharedMemorySize,
                         ATT_SMEM_BYTES);
    cudaFuncSetAttribute(hmma_gemm_kernel<0>,
                         cudaFuncAttributeMaxDynamicSharedMemorySize,
                         GEMM_SMEM);
    cudaFuncSetAttribute(hmma_gemm_kernel<1>,
                         cudaFuncAttributeMaxDynamicSharedMemorySize,
                         GEMM_SMEM);

    const int nA = MROWS * DM;
    const dim3 sp_grid(nA / 4 / 256, 1, 3);
    const dim3 tr_blk(32, 8);
    const dim3 mm_grid3(DM / 128, MROWS / 128, 3);
    const dim3 mm_grid1(DM / 128, MROWS / 128, 1);
    const dim3 vt_grid(LL / 32, DH / 32, NB * HH);

    pe_split_kernel<<<2048 * DH / 4 / 256, 256>>>(pe, PEhp);

    // fused Q/K/V projection chain
    split3_kernel<<<sp_grid, 256>>>(q_in, k_in, v_in, Ahp, Alp, nA);
    splitT3_kernel<<<dim3(DM / 32, DM / 32, 3), tr_blk>>>(Wq, Wk, Wv,
                                                          BhTp, BlTp);
    hmma_gemm_kernel<1><<<mm_grid3, 256, GEMM_SMEM>>>(
        Ahp, Alp, BhTp, BlTp, bq, bk, bv, nullptr, QKVhp, QKVlp);

    vtrans_kernel<<<vt_grid, dim3(32, 8)>>>(QKVhp + 2 * MA, QKVlp + 2 * MA,
                                            VhTp, VlTp);

    rel_attn_hmma_kernel<<<dim3(LL / 64, NB * HH), 128, ATT_SMEM_BYTES>>>(
        QKVhp, QKVlp, QKVhp + MA, QKVlp + MA, VhTp, VlTp, PEhp, AOhp, AOlp);

    // out = AO @ Wo + bo
    splitT3_kernel<<<dim3(DM / 32, DM / 32, 1), tr_blk>>>(Wo, Wo, Wo,
                                                          BhTp, BlTp);
    hmma_gemm_kernel<0><<<mm_grid1, 256, GEMM_SMEM>>>(
        AOhp, AOlp, BhTp, BlTp, bo, bo, bo, out, nullptr, nullptr);
}

// round 16
// speedup vs baseline: 2.7901x; 1.0616x over previous
#include <cuda_runtime.h>
#include <cuda_bf16.h>
#include <cstdint>

// Problem constants
#define DM     1024
#define NB     4
#define LL     1024
#define HH     16
#define DH     64
#define MROWS  (NB * LL)
#define MA     ((size_t)MROWS * DM)     // per-z A/out stride
#define MB     ((size_t)DM * DM)        // per-z weight stride

typedef __nv_bfloat16 bf16;

// -------- scratch (allocation-free: __device__ globals) --------
__device__ bf16 g_Ah[3 * MROWS * DM];
__device__ bf16 g_Al[3 * MROWS * DM];
__device__ bf16 g_BhT[3 * DM * DM];
__device__ bf16 g_BlT[3 * DM * DM];
__device__ bf16 g_QKVh[3 * MROWS * DM];   // [Qh | Kh | Vh]
__device__ bf16 g_QKVl[3 * MROWS * DM];   // [Ql | Kl | Vl]
__device__ bf16 g_VhT[MROWS * DM], g_VlT[MROWS * DM];   // [n][h][d][j]
__device__ bf16 g_AOh[MROWS * DM], g_AOl[MROWS * DM];
__device__ bf16 g_PEh[2048 * DH];

// =========================== helpers =======================================
__device__ __forceinline__ uint32_t smem_to_u32(const void* p) {
    uint32_t a;
    asm("{ .reg .u64 t; cvta.to.shared.u64 t, %1; cvt.u32.u64 %0, t; }"
        : "=r"(a) : "l"(p));
    return a;
}

#define LDMX4(r, addr)                                                        \
    asm volatile("ldmatrix.sync.aligned.m8n8.x4.shared.b16 "                  \
                 "{%0,%1,%2,%3}, [%4];"                                       \
                 : "=r"((r)[0]), "=r"((r)[1]), "=r"((r)[2]), "=r"((r)[3])     \
                 : "r"(addr))

__device__ __forceinline__ void mma_bf16(float* d, const uint32_t* a,
                                         uint32_t b0, uint32_t b1) {
    asm volatile(
        "mma.sync.aligned.m16n8k16.row.col.f32.bf16.bf16.f32 "
        "{%0,%1,%2,%3}, {%4,%5,%6,%7}, {%8,%9}, {%0,%1,%2,%3};"
        : "+f"(d[0]), "+f"(d[1]), "+f"(d[2]), "+f"(d[3])
        : "r"(a[0]), "r"(a[1]), "r"(a[2]), "r"(a[3]), "r"(b0), "r"(b1));
}

__device__ __forceinline__ void cpa16(uint32_t dst, const void* src) {
    asm volatile("cp.async.cg.shared.global [%0], [%1], 16;"
                 :: "r"(dst), "l"(src));
}
#define CP_COMMIT() asm volatile("cp.async.commit_group;")
#define CP_WAIT(n)  asm volatile("cp.async.wait_group %0;" :: "n"(n))

// fast exp on fma pipe (x <= 0)
__device__ __forceinline__ float fast_exp(float x) {
    float y = fmaxf(x * 1.44269504f, -126.0f);
    float r = rintf(y);
    float f = y - r;
    int   e = (int)r;
    float p = 1.33336e-3f;
    p = fmaf(p, f, 9.61812e-3f);
    p = fmaf(p, f, 5.55041e-2f);
    p = fmaf(p, f, 2.40226e-1f);
    p = fmaf(p, f, 6.93147e-1f);
    p = fmaf(p, f, 1.0f);
    return __int_as_float(__float_as_int(p) + (e << 23));
}

__device__ __forceinline__ uint32_t pack_bf2(float a, float b) {
    __nv_bfloat162 t = __halves2bfloat162(__float2bfloat16_rn(a),
                                          __float2bfloat16_rn(b));
    return *reinterpret_cast<uint32_t*>(&t);
}
__device__ __forceinline__ void split2(float v0, float v1,
                                       uint32_t& hi, uint32_t& lo) {
    bf16 h0 = __float2bfloat16_rn(v0), h1 = __float2bfloat16_rn(v1);
    __nv_bfloat162 th = __halves2bfloat162(h0, h1);
    hi = *reinterpret_cast<uint32_t*>(&th);
    lo = pack_bf2(v0 - __bfloat162float(h0), v1 - __bfloat162float(h1));
}

// ===========================================================================
// fused split of 3 inputs: fp32 -> (hi, lo) bf16, z selects tensor
// ===========================================================================
__global__ void split3_kernel(const float* __restrict__ X0,
                              const float* __restrict__ X1,
                              const float* __restrict__ X2,
                              bf16* __restrict__ H, bf16* __restrict__ L,
                              int n)
{
    const int z = blockIdx.z;
    const float* X = (z == 0) ? X0 : (z == 1) ? X1 : X2;
    const size_t zo = (size_t)z * n;
    int i = (blockIdx.x * blockDim.x + threadIdx.x) * 4;
    if (i >= n) return;
    float4 v = *(const float4*)(X + i);
    uint32_t h01, l01, h23, l23;
    split2(v.x, v.y, h01, l01);
    split2(v.z, v.w, h23, l23);
    *(uint32_t*)(H + zo + i)     = h01;
    *(uint32_t*)(H + zo + i + 2) = h23;
    *(uint32_t*)(L + zo + i)     = l01;
    *(uint32_t*)(L + zo + i + 2) = l23;
}

// ===========================================================================
// fused transpose + split of up to 3 weights: W[K][N] -> HT/LT[N][K], z-sel
// ===========================================================================
__global__ void splitT3_kernel(const float* __restrict__ W0,
                               const float* __restrict__ W1,
                               const float* __restrict__ W2,
                               bf16* __restrict__ HT, bf16* __restrict__ LT)
{
    __shared__ float t[32][33];
    const int z = blockIdx.z;
    const float* W = (z == 0) ? W0 : (z == 1) ? W1 : W2;
    const size_t zo = (size_t)z * MB;
    const int bx = blockIdx.x * 32;
    const int by = blockIdx.y * 32;
    const int x = threadIdx.x, y = threadIdx.y;
    #pragma unroll
    for (int j = 0; j < 32; j += 8)
        t[y + j][x] = W[(size_t)(by + y + j) * DM + bx + x];
    __syncthreads();
    #pragma unroll
    for (int j = 0; j < 32; j += 8) {
        float v = t[x][y + j];
        bf16 h = __float2bfloat16_rn(v);
        bf16 l = __float2bfloat16_rn(v - __bfloat162float(h));
        size_t o = zo + (size_t)(bx + y + j) * DM + by + x;
        HT[o] = h;
        LT[o] = l;
    }
}

// ===========================================================================
// bf16 per-head transpose of V
// ===========================================================================
__global__ void vtrans_kernel(const bf16* __restrict__ Vh,
                              const bf16* __restrict__ Vl,
                              bf16* __restrict__ VhT,
                              bf16* __restrict__ VlT)
{
    __shared__ bf16 th[32][34], tl[32][34];
    const int nh = blockIdx.z;
    const int n = nh >> 4, h = nh & 15;
    const int j0 = blockIdx.x * 32, d0 = blockIdx.y * 32;
    const int x = threadIdx.x, y = threadIdx.y;   // 32 x 8
    #pragma unroll
    for (int jj = 0; jj < 32; jj += 8) {
        size_t src = (size_t)(n * LL + j0 + y + jj) * DM + h * DH + d0 + x;
        th[y + jj][x] = Vh[src];
        tl[y + jj][x] = Vl[src];
    }
    __syncthreads();
    #pragma unroll
    for (int jj = 0; jj < 32; jj += 8) {
        size_t dst = (size_t)((n * HH + h) * DH + d0 + y + jj) * LL + j0 + x;
        VhT[dst] = th[x][y + jj];
        VlT[dst] = tl[x][y + jj];
    }
}

// ===========================================================================
// PE -> bf16 (hi only)
// ===========================================================================
__global__ void pe_split_kernel(const float* __restrict__ PE,
                                bf16* __restrict__ PEh)
{
    int i = (blockIdx.x * blockDim.x + threadIdx.x) * 4;
    if (i >= 2048 * DH) return;
    float4 v = *(const float4*)(PE + i);
    *(uint32_t*)(PEh + i)     = pack_bf2(v.x, v.y);
    *(uint32_t*)(PEh + i + 2) = pack_bf2(v.z, v.w);
}

// ===========================================================================
// HMMA split-bf16 GEMM, cp.async double-buffered.
// 2 CTAs/SM enforced (128-reg cap); A-fragment registers reused between
// the Ah passes and the Al pass to stay under the cap without spills.
// grid.z selects (A,B,bias,out) tuple; M=MROWS, N=K=DM fixed.
// ===========================================================================
#define SK 40
#define STG_BYTES (128 * SK * 2)            // 10240 per array
#define GEMM_SMEM (2 * 4 * STG_BYTES)       // 81920

template <int SPLIT_OUT>
__global__ __launch_bounds__(256, 2)
void hmma_gemm_kernel(const bf16* __restrict__ Ahg, const bf16* __restrict__ Alg,
                      const bf16* __restrict__ BhTg, const bf16* __restrict__ BlTg,
                      const float* __restrict__ bias0,
                      const float* __restrict__ bias1,
                      const float* __restrict__ bias2,
                      float* __restrict__ C,
                      bf16* __restrict__ Chg, bf16* __restrict__ Clg)
{
    extern __shared__ char gsm[];
    const uint32_t smem0 = smem_to_u32(gsm);

    const int z = blockIdx.z;
    const float* bias = (z == 0) ? bias0 : (z == 1) ? bias1 : bias2;
    const bf16* Ah  = Ahg  + (size_t)z * MA;
    const bf16* Al  = Alg  + (size_t)z * MA;
    const bf16* BhT = BhTg + (size_t)z * MB;
    const bf16* BlT = BlTg + (size_t)z * MB;
    bf16* Ch = SPLIT_OUT ? (Chg + (size_t)z * MA) : nullptr;
    bf16* Cl = SPLIT_OUT ? (Clg + (size_t)z * MA) : nullptr;

    const int tid  = threadIdx.x;
    const int lane = tid & 31;
    const int wid  = tid >> 5;
    const int wm   = wid & 1;
    const int wn   = wid >> 1;
    const int row0 = blockIdx.y * 128;
    const int col0 = blockIdx.x * 128;

    float acc[4][4][4];
    #pragma unroll
    for (int i = 0; i < 4; ++i)
        #pragma unroll
        for (int j = 0; j < 4; ++j)
            #pragma unroll
            for (int k = 0; k < 4; ++k) acc[i][j][k] = 0.f;

    const int aRow = wm * 64 + ((lane >> 3) & 1) * 8 + (lane & 7);
    const int aK   = ((lane >> 4) & 1) * 8;
    const int bRow = wn * 32 + ((lane >> 4) & 1) * 8 + (lane & 7);
    const int bK   = ((lane >> 3) & 1) * 8;
    const uint32_t laneA = (uint32_t)(aRow * SK + aK) * 2;
    const uint32_t laneB = (uint32_t)(bRow * SK + bK) * 2;

    const bf16* srcs[4] = { Ah + (size_t)row0 * DM, Al + (size_t)row0 * DM,
                            BhT + (size_t)col0 * DM, BlT + (size_t)col0 * DM };

    const int lr = tid >> 2;             // 0..63
    const int lc = (tid & 3) * 8;        // 0,8,16,24

    // prefetch stage 0
    #pragma unroll
    for (int a = 0; a < 4; ++a) {
        const bf16* src = srcs[a];
        uint32_t d0 = smem0 + a * STG_BYTES + lr * (SK * 2) + lc * 2;
        cpa16(d0, src + (size_t)lr * DM + lc);
        cpa16(d0 + 64 * (SK * 2), src + (size_t)(lr + 64) * DM + lc);
    }
    CP_COMMIT();

    const int nIter = DM / 32;
    for (int it = 0; it < nIter; ++it) {
        const int s = it & 1;
        CP_WAIT(0);
        __syncthreads();
        if (it + 1 < nIter) {
            const int kc = (it + 1) * 32;
            const uint32_t base = smem0 + (s ^ 1) * (4 * STG_BYTES);
            #pragma unroll
            for (int a = 0; a < 4; ++a) {
                const bf16* src = srcs[a] + kc;
                uint32_t d0 = base + a * STG_BYTES + lr * (SK * 2) + lc * 2;
                cpa16(d0, src + (size_t)lr * DM + lc);
                cpa16(d0 + 64 * (SK * 2), src + (size_t)(lr + 64) * DM + lc);
            }
            CP_COMMIT();
        }

        const uint32_t base = smem0 + s * (4 * STG_BYTES);
        const uint32_t uAh = base + laneA;
        const uint32_t uAl = base + STG_BYTES + laneA;
        const uint32_t uBh = base + 2 * STG_BYTES + laneB;
        const uint32_t uBl = base + 3 * STG_BYTES + laneB;

        #pragma unroll
        for (int ks = 0; ks < 32; ks += 16) {
            // af holds Ah for passes 1-2, then is overwritten with Al for
            // pass 3 -> max live fragment regs 32 instead of 48.
            uint32_t af[4][4], bhf[2][4], blf[2][4];
            #pragma unroll
            for (int mt = 0; mt < 4; ++mt)
                LDMX4(af[mt], uAh + mt * (16 * SK * 2) + ks * 2);
            #pragma unroll
            for (int p = 0; p < 2; ++p) {
                LDMX4(bhf[p], uBh + p * (16 * SK * 2) + ks * 2);
                LDMX4(blf[p], uBl + p * (16 * SK * 2) + ks * 2);
            }
            // pass 1: Ah * Bh
            #pragma unroll
            for (int mt = 0; mt < 4; ++mt)
                #pragma unroll
                for (int nt = 0; nt < 4; ++nt)
                    mma_bf16(acc[mt][nt], af[mt],
                             bhf[nt >> 1][(nt & 1) * 2],
                             bhf[nt >> 1][(nt & 1) * 2 + 1]);
            // pass 2: Ah * Bl
            #pragma unroll
            for (int mt = 0; mt < 4; ++mt)
                #pragma unroll
                for (int nt = 0; nt < 4; ++nt)
                    mma_bf16(acc[mt][nt], af[mt],
                             blf[nt >> 1][(nt & 1) * 2],
                             blf[nt >> 1][(nt & 1) * 2 + 1]);
            // reload af with Al (Ah dead), pass 3: Al * Bh
            #pragma unroll
            for (int mt = 0; mt < 4; ++mt)
                LDMX4(af[mt], uAl + mt * (16 * SK * 2) + ks * 2);
            #pragma unroll
            for (int mt = 0; mt < 4; ++mt)
                #pragma unroll
                for (int nt = 0; nt < 4; ++nt)
                    mma_bf16(acc[mt][nt], af[mt],
                             bhf[nt >> 1][(nt & 1) * 2],
                             bhf[nt >> 1][(nt & 1) * 2 + 1]);
        }
        __syncthreads();
    }

    #pragma unroll
    for (int mt = 0; mt < 4; ++mt) {
        const int r1 = row0 + wm * 64 + mt * 16 + (lane >> 2);
        const int r2 = r1 + 8;
        #pragma unroll
        for (int nt = 0; nt < 4; ++nt) {
            const int c = col0 + wn * 32 + nt * 8 + (lane & 3) * 2;
            const float b0 = bias[c], b1 = bias[c + 1];
            const float v0 = acc[mt][nt][0] + b0, v1 = acc[mt][nt][1] + b1;
            const float v2 = acc[mt][nt][2] + b0, v3 = acc[mt][nt][3] + b1;
            if (SPLIT_OUT) {
                uint32_t hi, lo;
                split2(v0, v1, hi, lo);
                *(uint32_t*)(Ch + (size_t)r1 * DM + c) = hi;
                *(uint32_t*)(Cl + (size_t)r1 * DM + c) = lo;
                split2(v2, v3, hi, lo);
                *(uint32_t*)(Ch + (size_t)r2 * DM + c) = hi;
                *(uint32_t*)(Cl + (size_t)r2 * DM + c) = lo;
            } else {
                *(float2*)(C + (size_t)r1 * DM + c) = make_float2(v0, v1);
                *(float2*)(C + (size_t)r2 * DM + c) = make_float2(v2, v3);
            }
        }
    }
}

// ===========================================================================
// HMMA flash attention with relative-position bias (unchanged from R15).
// ===========================================================================
#define ATT_SMEM_BYTES (6 * 64 * 72 * 2 + 128 * 72 * 2 + 64 * 136 * 4)

__global__ __launch_bounds__(128)
void rel_attn_hmma_kernel(const bf16* __restrict__ Qhg,
                          const bf16* __restrict__ Qlg,
                          const bf16* __restrict__ Khg,
                          const bf16* __restrict__ Klg,
                          const bf16* __restrict__ VhTg,
                          const bf16* __restrict__ VlTg,
                          const bf16* __restrict__ PEhg,
                          bf16* __restrict__ AOh,
                          bf16* __restrict__ AOl)
{
    extern __shared__ char smx[];
    bf16* sQh = (bf16*)smx;
    bf16* sQl = sQh + 64 * 72;
    bf16* sKh = sQl + 64 * 72;
    bf16* sKl = sKh + 64 * 72;
    bf16* sVh = sKl + 64 * 72;   // V^T: [d][j]
    bf16* sVl = sVh + 64 * 72;
    bf16* sPE = sVl + 64 * 72;   // [128][72]
    float* sQPE = (float*)(sPE + 128 * 72);  // [64][136]

    const int tid  = threadIdx.x;
    const int lane = tid & 31;
    const int w    = tid >> 5;
    const int qt   = (int)gridDim.x - 1 - (int)blockIdx.x;
    const int l0   = qt * 64;
    const int n    = blockIdx.y >> 4;
    const int h    = blockIdx.y & 15;

    {
        const bf16* qh = Qhg + ((size_t)(n * LL + l0)) * DM + h * DH;
        const bf16* ql = Qlg + ((size_t)(n * LL + l0)) * DM + h * DH;
        for (int t = tid; t < 64 * 8; t += 128) {
            int r = t >> 3, c8 = (t & 7) * 8;
            *(uint4*)(sQh + r * 72 + c8) = *(const uint4*)(qh + (size_t)r * DM + c8);
            *(uint4*)(sQl + r * 72 + c8) = *(const uint4*)(ql + (size_t)r * DM + c8);
        }
    }
    __syncthreads();

    const int aRow = w * 16 + ((lane >> 3) & 1) * 8 + (lane & 7);
    const int aK   = ((lane >> 4) & 1) * 8;
    const int bRow = ((lane >> 4) & 1) * 8 + (lane & 7);
    const int bK   = ((lane >> 3) & 1) * 8;

    uint32_t qh[4][4], ql[4][4];
    {
        const uint32_t uQh = smem_to_u32(sQh + aRow * 72 + aK);
        const uint32_t uQl = smem_to_u32(sQl + aRow * 72 + aK);
        #pragma unroll
        for (int ks = 0; ks < 4; ++ks) {
            LDMX4(qh[ks], uQh + ks * 32);
            LDMX4(ql[ks], uQl + ks * 32);
        }
    }

    float o[8][4];
    #pragma unroll
    for (int i = 0; i < 8; ++i)
        #pragma unroll
        for (int j = 0; j < 4; ++j) o[i][j] = 0.f;
    float m0 = -1e30f, m1 = -1e30f, ls0acc = 0.f, ls1acc = 0.f;

    const int r0q = lane >> 2, c0 = (lane & 3) * 2;
    const int il0 = w * 16 + r0q, il1 = il0 + 8;
    const float* qpe0 = sQPE + il0 * 136 + 63 - il0;
    const float* qpe1 = sQPE + il1 * 136 + 63 - il1;
    float* qw0 = sQPE + il0 * 136 + c0;
    float* qw1 = sQPE + il1 * 136 + c0;

    for (int jt = 0; jt <= qt; ++jt) {
        const int j0 = jt * 64;

        {
            const bf16* kh = Khg + ((size_t)(n * LL + j0)) * DM + h * DH;
            const bf16* kl = Klg + ((size_t)(n * LL + j0)) * DM + h * DH;
            const bf16* vh = VhTg + ((size_t)((n * HH + h) * DH)) * LL + j0;
            const bf16* vl = VlTg + ((size_t)((n * HH + h) * DH)) * LL + j0;
            for (int t = tid; t < 64 * 8; t += 128) {
                int r = t >> 3, c8 = (t & 7) * 8;
                *(uint4*)(sKh + r * 72 + c8) = *(const uint4*)(kh + (size_t)r * DM + c8);
                *(uint4*)(sKl + r * 72 + c8) = *(const uint4*)(kl + (size_t)r * DM + c8);
                *(uint4*)(sVh + r * 72 + c8) = *(const uint4*)(vh + (size_t)r * LL + c8);
                *(uint4*)(sVl + r * 72 + c8) = *(const uint4*)(vl + (size_t)r * LL + c8);
            }
            const int pebase = 1984 - l0 + j0;
            for (int t = tid; t < 128 * 8; t += 128) {
                int r = t >> 3, c8 = (t & 7) * 8;
                int gr = pebase + r;
                uint4 v = make_uint4(0u, 0u, 0u, 0u);
                if (gr < 2048) v = *(const uint4*)(PEhg + (size_t)gr * DH + c8);
                *(uint4*)(sPE + r * 72 + c8) = v;
            }
        }
        __syncthreads();

        // ---- QPE = Qh @ PEband^T ----
        {
            float pacc[16][4];
            #pragma unroll
            for (int i = 0; i < 16; ++i)
                #pragma unroll
                for (int j = 0; j < 4; ++j) pacc[i][j] = 0.f;
            const uint32_t uPE = smem_to_u32(sPE + bRow * 72 + bK);
            #pragma unroll
            for (int ks = 0; ks < 4; ++ks) {
                uint32_t pf[8][4];
                #pragma unroll
                for (int p = 0; p < 8; ++p)
                    LDMX4(pf[p], uPE + p * (16 * 72 * 2) + ks * 32);
                #pragma unroll
                for (int nt = 0; nt < 16; ++nt)
                    mma_bf16(pacc[nt], qh[ks],
                             pf[nt >> 1][(nt & 1) * 2],
                             pf[nt >> 1][(nt & 1) * 2 + 1]);
            }
            #pragma unroll
            for (int nt = 0; nt < 16; ++nt) {
                qw0[nt * 8]     = pacc[nt][0];
                qw0[nt * 8 + 1] = pacc[nt][1];
                qw1[nt * 8]     = pacc[nt][2];
                qw1[nt * 8 + 1] = pacc[nt][3];
            }
            __syncwarp();
        }

        // ---- S = Q K^T (3 passes, pass-major) ----
        float s[8][4];
        #pragma unroll
        for (int i = 0; i < 8; ++i)
            #pragma unroll
            for (int j = 0; j < 4; ++j) s[i][j] = 0.f;
        {
            const uint32_t uKh = smem_to_u32(sKh + bRow * 72 + bK);
            const uint32_t uKl = smem_to_u32(sKl + bRow * 72 + bK);
            #pragma unroll
            for (int ks = 0; ks < 4; ++ks) {
                uint32_t kh[4][4], kl[4][4];
                #pragma unroll
                for (int p = 0; p < 4; ++p) {
                    LDMX4(kh[p], uKh + p * (16 * 72 * 2) + ks * 32);
                    LDMX4(kl[p], uKl + p * (16 * 72 * 2) + ks * 32);
                }
                #pragma unroll
                for (int nt = 0; nt < 8; ++nt)
                    mma_bf16(s[nt], qh[ks], kh[nt >> 1][(nt & 1) * 2],
                             kh[nt >> 1][(nt & 1) * 2 + 1]);
                #pragma unroll
                for (int nt = 0; nt < 8; ++nt)
                    mma_bf16(s[nt], qh[ks], kl[nt >> 1][(nt & 1) * 2],
                             kl[nt >> 1][(nt & 1) * 2 + 1]);
                #pragma unroll
                for (int nt = 0; nt < 8; ++nt)
                    mma_bf16(s[nt], ql[ks], kh[nt >> 1][(nt & 1) * 2],
                             kh[nt >> 1][(nt & 1) * 2 + 1]);
            }
        }

        // ---- bias + scale + mask + online softmax ----
        const bool bd = (jt == qt);
        float rmax0 = -1e30f, rmax1 = -1e30f;
        #pragma unroll
        for (int nt = 0; nt < 8; ++nt) {
            #pragma unroll
            for (int e = 0; e < 2; ++e) {
                const int jl = nt * 8 + c0 + e;
                float v0 = (s[nt][e] + qpe0[jl]) * 0.125f;
                if (bd && jl > il0) v0 = -1e9f;
                s[nt][e] = v0;
                rmax0 = fmaxf(rmax0, v0);
                float v1 = (s[nt][e + 2] + qpe1[jl]) * 0.125f;
                if (bd && jl > il1) v1 = -1e9f;
                s[nt][e + 2] = v1;
                rmax1 = fmaxf(rmax1, v1);
            }
        }
        rmax0 = fmaxf(rmax0, __shfl_xor_sync(0xffffffffu, rmax0, 1));
        rmax0 = fmaxf(rmax0, __shfl_xor_sync(0xffffffffu, rmax0, 2));
        rmax1 = fmaxf(rmax1, __shfl_xor_sync(0xffffffffu, rmax1, 1));
        rmax1 = fmaxf(rmax1, __shfl_xor_sync(0xffffffffu, rmax1, 2));

        const float mn0 = fmaxf(m0, rmax0), mn1 = fmaxf(m1, rmax1);
        const float a0 = fast_exp(m0 - mn0), a1 = fast_exp(m1 - mn1);
        m0 = mn0; m1 = mn1;

        float ls0 = 0.f, ls1 = 0.f;
        uint32_t pah[4][4], pal[4][4];
        #pragma unroll
        for (int nt = 0; nt < 8; ++nt) {
            float p0 = fast_exp(s[nt][0] - m0);
            float p1 = fast_exp(s[nt][1] - m0);
            float p2 = fast_exp(s[nt][2] - m1);
            float p3 = fast_exp(s[nt][3] - m1);
            ls0 += p0 + p1; ls1 += p2 + p3;
            const int kt = nt >> 1, off = (nt & 1) * 2;
            uint32_t hi01, lo01, hi23, lo23;
            split2(p0, p1, hi01, lo01);
            split2(p2, p3, hi23, lo23);
            pah[kt][off]     = hi01;
            pah[kt][off + 1] = hi23;
            pal[kt][off]     = lo01;
            pal[kt][off + 1] = lo23;
        }
        ls0acc = ls0acc * a0 + ls0;
        ls1acc = ls1acc * a1 + ls1;
        #pragma unroll
        for (int nt = 0; nt < 8; ++nt) {
            o[nt][0] *= a0; o[nt][1] *= a0;
            o[nt][2] *= a1; o[nt][3] *= a1;
        }

        // ---- O += P V (3 passes, pass-major) ----
        {
            const uint32_t uVh = smem_to_u32(sVh + bRow * 72 + bK);
            const uint32_t uVl = smem_to_u32(sVl + bRow * 72 + bK);
            #pragma unroll
            for (int kt = 0; kt < 4; ++kt) {
                uint32_t vh[4][4], vl[4][4];
                #pragma unroll
                for (int p = 0; p < 4; ++p) {
                    LDMX4(vh[p], uVh + p * (16 * 72 * 2) + kt * 32);
                    LDMX4(vl[p], uVl + p * (16 * 72 * 2) + kt * 32);
                }
                #pragma unroll
                for (int dt = 0; dt < 8; ++dt)
                    mma_bf16(o[dt], pah[kt], vh[dt >> 1][(dt & 1) * 2],
                             vh[dt >> 1][(dt & 1) * 2 + 1]);
                #pragma unroll
                for (int dt = 0; dt < 8; ++dt)
                    mma_bf16(o[dt], pah[kt], vl[dt >> 1][(dt & 1) * 2],
                             vl[dt >> 1][(dt & 1) * 2 + 1]);
                #pragma unroll
                for (int dt = 0; dt < 8; ++dt)
                    mma_bf16(o[dt], pal[kt], vh[dt >> 1][(dt & 1) * 2],
                             vh[dt >> 1][(dt & 1) * 2 + 1]);
            }
        }
        __syncthreads();
    }

    // ---- epilogue ----
    float lt0 = ls0acc, lt1 = ls1acc;
    lt0 += __shfl_xor_sync(0xffffffffu, lt0, 1);
    lt0 += __shfl_xor_sync(0xffffffffu, lt0, 2);
    lt1 += __shfl_xor_sync(0xffffffffu, lt1, 1);
    lt1 += __shfl_xor_sync(0xffffffffu, lt1, 2);
    const float inv0 = 1.0f / lt0, inv1 = 1.0f / lt1;
    bf16* oh0 = AOh + ((size_t)(n * LL + l0 + il0)) * DM + h * DH;
    bf16* ol0 = AOl + ((size_t)(n * LL + l0 + il0)) * DM + h * DH;
    bf16* oh1 = AOh + ((size_t)(n * LL + l0 + il1)) * DM + h * DH;
    bf16* ol1 = AOl + ((size_t)(n * LL + l0 + il1)) * DM + h * DH;
    #pragma unroll
    for (int nt = 0; nt < 8; ++nt) {
        uint32_t hi, lo;
        split2(o[nt][0] * inv0, o[nt][1] * inv0, hi, lo);
        *(uint32_t*)(oh0 + nt * 8 + c0) = hi;
        *(uint32_t*)(ol0 + nt * 8 + c0) = lo;
        split2(o[nt][2] * inv1, o[nt][3] * inv1, hi, lo);
        *(uint32_t*)(oh1 + nt * 8 + c0) = hi;
        *(uint32_t*)(ol1 + nt * 8 + c0) = lo;
    }
}

// ===========================================================================
extern "C" void kernel_launch(void* const* d_in, const int* in_sizes, int n_in,
                              void* d_out, int out_size)
{
    const float* q_in = (const float*)d_in[0];
    const float* k_in = (const float*)d_in[1];
    const float* v_in = (const float*)d_in[2];
    const float* Wq = (const float*)d_in[4];
    const float* bq = (const float*)d_in[5];
    const float* Wk = (const float*)d_in[6];
    const float* bk = (const float*)d_in[7];
    const float* Wv = (const float*)d_in[8];
    const float* bv = (const float*)d_in[9];
    const float* Wo = (const float*)d_in[10];
    const float* bo = (const float*)d_in[11];
    const float* pe = (const float*)d_in[12];
    float* out = (float*)d_out;

    bf16 *Ahp, *Alp, *BhTp, *BlTp, *QKVhp, *QKVlp;
    bf16 *VhTp, *VlTp, *AOhp, *AOlp, *PEhp;
    cudaGetSymbolAddress((void**)&Ahp,   g_Ah);
    cudaGetSymbolAddress((void**)&Alp,   g_Al);
    cudaGetSymbolAddress((void**)&BhTp,  g_BhT);
    cudaGetSymbolAddress((void**)&BlTp,  g_BlT);
    cudaGetSymbolAddress((void**)&QKVhp, g_QKVh);
    cudaGetSymbolAddress((void**)&QKVlp, g_QKVl);
    cudaGetSymbolAddress((void**)&VhTp,  g_VhT);
    cudaGetSymbolAddress((void**)&VlTp,  g_VlT);
    cudaGetSymbolAddress((void**)&AOhp,  g_AOh);
    cudaGetSymbolAddress((void**)&AOlp,  g_AOl);
    cudaGetSymbolAddress((void**)&PEhp,  g_PEh);

    cudaFuncSetAttribute(rel_attn_hmma_kernel,
                         cudaFuncAttributeMaxDynamicSharedMemorySize,
                         ATT_SMEM_BYTES);
    cudaFuncSetAttribute(hmma_gemm_kernel<0>,
                         cudaFuncAttributeMaxDynamicSharedMemorySize,
                         GEMM_SMEM);
    cudaFuncSetAttribute(hmma_gemm_kernel<1>,
                         cudaFuncAttributeMaxDynamicSharedMemorySize,
                         GEMM_SMEM);

    const int nA = MROWS * DM;
    const dim3 sp_grid(nA / 4 / 256, 1, 3);
    const dim3 tr_blk(32, 8);
    const dim3 mm_grid3(DM / 128, MROWS / 128, 3);
    const dim3 mm_grid1(DM / 128, MROWS / 128, 1);
    const dim3 vt_grid(LL / 32, DH / 32, NB * HH);

    pe_split_kernel<<<2048 * DH / 4 / 256, 256>>>(pe, PEhp);

    // fused Q/K/V projection chain
    split3_kernel<<<sp_grid, 256>>>(q_in, k_in, v_in, Ahp, Alp, nA);
    splitT3_kernel<<<dim3(DM / 32, DM / 32, 3), tr_blk>>>(Wq, Wk, Wv,
                                                          BhTp, BlTp);
    hmma_gemm_kernel<1><<<mm_grid3, 256, GEMM_SMEM>>>(
        Ahp, Alp, BhTp, BlTp, bq, bk, bv, nullptr, QKVhp, QKVlp);

    vtrans_kernel<<<vt_grid, dim3(32, 8)>>>(QKVhp + 2 * MA, QKVlp + 2 * MA,
                                            VhTp, VlTp);

    rel_attn_hmma_kernel<<<dim3(LL / 64, NB * HH), 128, ATT_SMEM_BYTES>>>(
        QKVhp, QKVlp, QKVhp + MA, QKVlp + MA, VhTp, VlTp, PEhp, AOhp, AOlp);

    // out = AO @ Wo + bo
    splitT3_kernel<<<dim3(DM / 32, DM / 32, 1), tr_blk>>>(Wo, Wo, Wo,
                                                          BhTp, BlTp);
    hmma_gemm_kernel<0><<<mm_grid1, 256, GEMM_SMEM>>>(
        AOhp, AOlp, BhTp, BlTp, bo, bo, bo, out, nullptr, nullptr);
}

// round 17
// speedup vs baseline: 3.1330x; 1.1229x over previous
#include <cuda_runtime.h>
#include <cuda_bf16.h>
#include <cstdint>

// Problem constants
#define DM     1024
#define NB     4
#define LL     1024
#define HH     16
#define DH     64
#define MROWS  (NB * LL)
#define MA     ((size_t)MROWS * DM)     // per-z A/out stride
#define MB     ((size_t)DM * DM)        // per-z weight stride

typedef __nv_bfloat16 bf16;

// -------- scratch (allocation-free: __device__ globals) --------
__device__ bf16 g_Ah[3 * MROWS * DM];
__device__ bf16 g_Al[3 * MROWS * DM];
__device__ bf16 g_BhT[3 * DM * DM];
__device__ bf16 g_BlT[3 * DM * DM];
__device__ bf16 g_QKVh[3 * MROWS * DM];   // [Qh | Kh | Vh]
__device__ bf16 g_QKVl[3 * MROWS * DM];   // [Ql | Kl | Vl]
__device__ bf16 g_VhT[MROWS * DM], g_VlT[MROWS * DM];   // [n][h][d][j]
__device__ bf16 g_AOh[MROWS * DM], g_AOl[MROWS * DM];
__device__ bf16 g_PEh[2048 * DH];

// =========================== helpers =======================================
__device__ __forceinline__ uint32_t smem_to_u32(const void* p) {
    uint32_t a;
    asm("{ .reg .u64 t; cvta.to.shared.u64 t, %1; cvt.u32.u64 %0, t; }"
        : "=r"(a) : "l"(p));
    return a;
}

#define LDMX4(r, addr)                                                        \
    asm volatile("ldmatrix.sync.aligned.m8n8.x4.shared.b16 "                  \
                 "{%0,%1,%2,%3}, [%4];"                                       \
                 : "=r"((r)[0]), "=r"((r)[1]), "=r"((r)[2]), "=r"((r)[3])     \
                 : "r"(addr))

__device__ __forceinline__ void mma_bf16(float* d, const uint32_t* a,
                                         uint32_t b0, uint32_t b1) {
    asm volatile(
        "mma.sync.aligned.m16n8k16.row.col.f32.bf16.bf16.f32 "
        "{%0,%1,%2,%3}, {%4,%5,%6,%7}, {%8,%9}, {%0,%1,%2,%3};"
        : "+f"(d[0]), "+f"(d[1]), "+f"(d[2]), "+f"(d[3])
        : "r"(a[0]), "r"(a[1]), "r"(a[2]), "r"(a[3]), "r"(b0), "r"(b1));
}

__device__ __forceinline__ void cpa16(uint32_t dst, const void* src) {
    asm volatile("cp.async.cg.shared.global [%0], [%1], 16;"
                 :: "r"(dst), "l"(src));
}
#define CP_COMMIT() asm volatile("cp.async.commit_group;")
#define CP_WAIT(n)  asm volatile("cp.async.wait_group %0;" :: "n"(n))

// fast exp on fma pipe (x <= 0)
__device__ __forceinline__ float fast_exp(float x) {
    float y = fmaxf(x * 1.44269504f, -126.0f);
    float r = rintf(y);
    float f = y - r;
    int   e = (int)r;
    float p = 1.33336e-3f;
    p = fmaf(p, f, 9.61812e-3f);
    p = fmaf(p, f, 5.55041e-2f);
    p = fmaf(p, f, 2.40226e-1f);
    p = fmaf(p, f, 6.93147e-1f);
    p = fmaf(p, f, 1.0f);
    return __int_as_float(__float_as_int(p) + (e << 23));
}

__device__ __forceinline__ uint32_t pack_bf2(float a, float b) {
    __nv_bfloat162 t = __halves2bfloat162(__float2bfloat16_rn(a),
                                          __float2bfloat16_rn(b));
    return *reinterpret_cast<uint32_t*>(&t);
}
__device__ __forceinline__ void split2(float v0, float v1,
                                       uint32_t& hi, uint32_t& lo) {
    bf16 h0 = __float2bfloat16_rn(v0), h1 = __float2bfloat16_rn(v1);
    __nv_bfloat162 th = __halves2bfloat162(h0, h1);
    hi = *reinterpret_cast<uint32_t*>(&th);
    lo = pack_bf2(v0 - __bfloat162float(h0), v1 - __bfloat162float(h1));
}

// ===========================================================================
// fused split of 3 inputs: fp32 -> (hi, lo) bf16, z selects tensor
// ===========================================================================
__global__ void split3_kernel(const float* __restrict__ X0,
                              const float* __restrict__ X1,
                              const float* __restrict__ X2,
                              bf16* __restrict__ H, bf16* __restrict__ L,
                              int n)
{
    const int z = blockIdx.z;
    const float* X = (z == 0) ? X0 : (z == 1) ? X1 : X2;
    const size_t zo = (size_t)z * n;
    int i = (blockIdx.x * blockDim.x + threadIdx.x) * 4;
    if (i >= n) return;
    float4 v = *(const float4*)(X + i);
    uint32_t h01, l01, h23, l23;
    split2(v.x, v.y, h01, l01);
    split2(v.z, v.w, h23, l23);
    *(uint32_t*)(H + zo + i)     = h01;
    *(uint32_t*)(H + zo + i + 2) = h23;
    *(uint32_t*)(L + zo + i)     = l01;
    *(uint32_t*)(L + zo + i + 2) = l23;
}

// ===========================================================================
// fused transpose + split of up to 3 weights: W[K][N] -> HT/LT[N][K], z-sel
// ===========================================================================
__global__ void splitT3_kernel(const float* __restrict__ W0,
                               const float* __restrict__ W1,
                               const float* __restrict__ W2,
                               bf16* __restrict__ HT, bf16* __restrict__ LT)
{
    __shared__ float t[32][33];
    const int z = blockIdx.z;
    const float* W = (z == 0) ? W0 : (z == 1) ? W1 : W2;
    const size_t zo = (size_t)z * MB;
    const int bx = blockIdx.x * 32;
    const int by = blockIdx.y * 32;
    const int x = threadIdx.x, y = threadIdx.y;
    #pragma unroll
    for (int j = 0; j < 32; j += 8)
        t[y + j][x] = W[(size_t)(by + y + j) * DM + bx + x];
    __syncthreads();
    #pragma unroll
    for (int j = 0; j < 32; j += 8) {
        float v = t[x][y + j];
        bf16 h = __float2bfloat16_rn(v);
        bf16 l = __float2bfloat16_rn(v - __bfloat162float(h));
        size_t o = zo + (size_t)(bx + y + j) * DM + by + x;
        HT[o] = h;
        LT[o] = l;
    }
}

// ===========================================================================
// bf16 per-head transpose of V
// ===========================================================================
__global__ void vtrans_kernel(const bf16* __restrict__ Vh,
                              const bf16* __restrict__ Vl,
                              bf16* __restrict__ VhT,
                              bf16* __restrict__ VlT)
{
    __shared__ bf16 th[32][34], tl[32][34];
    const int nh = blockIdx.z;
    const int n = nh >> 4, h = nh & 15;
    const int j0 = blockIdx.x * 32, d0 = blockIdx.y * 32;
    const int x = threadIdx.x, y = threadIdx.y;   // 32 x 8
    #pragma unroll
    for (int jj = 0; jj < 32; jj += 8) {
        size_t src = (size_t)(n * LL + j0 + y + jj) * DM + h * DH + d0 + x;
        th[y + jj][x] = Vh[src];
        tl[y + jj][x] = Vl[src];
    }
    __syncthreads();
    #pragma unroll
    for (int jj = 0; jj < 32; jj += 8) {
        size_t dst = (size_t)((n * HH + h) * DH + d0 + y + jj) * LL + j0 + x;
        VhT[dst] = th[x][y + jj];
        VlT[dst] = tl[x][y + jj];
    }
}

// ===========================================================================
// PE -> bf16 (hi only)
// ===========================================================================
__global__ void pe_split_kernel(const float* __restrict__ PE,
                                bf16* __restrict__ PEh)
{
    int i = (blockIdx.x * blockDim.x + threadIdx.x) * 4;
    if (i >= 2048 * DH) return;
    float4 v = *(const float4*)(PE + i);
    *(uint32_t*)(PEh + i)     = pack_bf2(v.x, v.y);
    *(uint32_t*)(PEh + i + 2) = pack_bf2(v.z, v.w);
}

// ===========================================================================
// HMMA split-bf16 GEMM, cp.async double-buffered, single barrier per iter,
// LDSM issued before the prefetch burst. 2 CTAs/SM.
// grid.z selects (A,B,bias,out) tuple; M=MROWS, N=K=DM fixed.
// ===========================================================================
#define SK 40
#define STG_BYTES (128 * SK * 2)            // 10240 per array
#define GEMM_SMEM (2 * 4 * STG_BYTES)       // 81920

template <int SPLIT_OUT>
__global__ __launch_bounds__(256, 2)
void hmma_gemm_kernel(const bf16* __restrict__ Ahg, const bf16* __restrict__ Alg,
                      const bf16* __restrict__ BhTg, const bf16* __restrict__ BlTg,
                      const float* __restrict__ bias0,
                      const float* __restrict__ bias1,
                      const float* __restrict__ bias2,
                      float* __restrict__ C,
                      bf16* __restrict__ Chg, bf16* __restrict__ Clg)
{
    extern __shared__ char gsm[];
    const uint32_t smem0 = smem_to_u32(gsm);

    const int z = blockIdx.z;
    const float* bias = (z == 0) ? bias0 : (z == 1) ? bias1 : bias2;
    const bf16* Ah  = Ahg  + (size_t)z * MA;
    const bf16* Al  = Alg  + (size_t)z * MA;
    const bf16* BhT = BhTg + (size_t)z * MB;
    const bf16* BlT = BlTg + (size_t)z * MB;
    bf16* Ch = SPLIT_OUT ? (Chg + (size_t)z * MA) : nullptr;
    bf16* Cl = SPLIT_OUT ? (Clg + (size_t)z * MA) : nullptr;

    const int tid  = threadIdx.x;
    const int lane = tid & 31;
    const int wid  = tid >> 5;
    const int wm   = wid & 1;
    const int wn   = wid >> 1;
    const int row0 = blockIdx.y * 128;
    const int col0 = blockIdx.x * 128;

    float acc[4][4][4];
    #pragma unroll
    for (int i = 0; i < 4; ++i)
        #pragma unroll
        for (int j = 0; j < 4; ++j)
            #pragma unroll
            for (int k = 0; k < 4; ++k) acc[i][j][k] = 0.f;

    const int aRow = wm * 64 + ((lane >> 3) & 1) * 8 + (lane & 7);
    const int aK   = ((lane >> 4) & 1) * 8;
    const int bRow = wn * 32 + ((lane >> 4) & 1) * 8 + (lane & 7);
    const int bK   = ((lane >> 3) & 1) * 8;
    const uint32_t laneA = (uint32_t)(aRow * SK + aK) * 2;
    const uint32_t laneB = (uint32_t)(bRow * SK + bK) * 2;

    const bf16* srcs[4] = { Ah + (size_t)row0 * DM, Al + (size_t)row0 * DM,
                            BhT + (size_t)col0 * DM, BlT + (size_t)col0 * DM };

    const int lr = tid >> 2;             // 0..63
    const int lc = (tid & 3) * 8;        // 0,8,16,24

    // prefetch stage 0
    #pragma unroll
    for (int a = 0; a < 4; ++a) {
        const bf16* src = srcs[a];
        uint32_t d0 = smem0 + a * STG_BYTES + lr * (SK * 2) + lc * 2;
        cpa16(d0, src + (size_t)lr * DM + lc);
        cpa16(d0 + 64 * (SK * 2), src + (size_t)(lr + 64) * DM + lc);
    }
    CP_COMMIT();

    const int nIter = DM / 32;
    for (int it = 0; it < nIter; ++it) {
        const int s = it & 1;
        CP_WAIT(0);
        __syncthreads();

        const uint32_t base = smem0 + s * (4 * STG_BYTES);
        const uint32_t uAh = base + laneA;
        const uint32_t uAl = base + STG_BYTES + laneA;
        const uint32_t uBh = base + 2 * STG_BYTES + laneB;
        const uint32_t uBl = base + 3 * STG_BYTES + laneB;

        #pragma unroll
        for (int ks = 0; ks < 32; ks += 16) {
            // af holds Ah for passes 1-2, then is overwritten with Al for
            // pass 3 -> max live fragment regs 32 instead of 48.
            uint32_t af[4][4], bhf[2][4], blf[2][4];
            #pragma unroll
            for (int mt = 0; mt < 4; ++mt)
                LDMX4(af[mt], uAh + mt * (16 * SK * 2) + ks * 2);
            #pragma unroll
            for (int p = 0; p < 2; ++p) {
                LDMX4(bhf[p], uBh + p * (16 * SK * 2) + ks * 2);
                LDMX4(blf[p], uBl + p * (16 * SK * 2) + ks * 2);
            }
            // issue next-stage prefetch AFTER the first LDSM batch so MMAs
            // are not queued behind the LDGSTS burst on the LSU.
            if (ks == 0 && it + 1 < nIter) {
                const int kc = (it + 1) * 32;
                const uint32_t pb = smem0 + (s ^ 1) * (4 * STG_BYTES);
                #pragma unroll
                for (int a = 0; a < 4; ++a) {
                    const bf16* src = srcs[a] + kc;
                    uint32_t d0 = pb + a * STG_BYTES + lr * (SK * 2) + lc * 2;
                    cpa16(d0, src + (size_t)lr * DM + lc);
                    cpa16(d0 + 64 * (SK * 2), src + (size_t)(lr + 64) * DM + lc);
                }
                CP_COMMIT();
            }
            // pass 1: Ah * Bh
            #pragma unroll
            for (int mt = 0; mt < 4; ++mt)
                #pragma unroll
                for (int nt = 0; nt < 4; ++nt)
                    mma_bf16(acc[mt][nt], af[mt],
                             bhf[nt >> 1][(nt & 1) * 2],
                             bhf[nt >> 1][(nt & 1) * 2 + 1]);
            // pass 2: Ah * Bl
            #pragma unroll
            for (int mt = 0; mt < 4; ++mt)
                #pragma unroll
                for (int nt = 0; nt < 4; ++nt)
                    mma_bf16(acc[mt][nt], af[mt],
                             blf[nt >> 1][(nt & 1) * 2],
                             blf[nt >> 1][(nt & 1) * 2 + 1]);
            // reload af with Al (Ah dead), pass 3: Al * Bh
            #pragma unroll
            for (int mt = 0; mt < 4; ++mt)
                LDMX4(af[mt], uAl + mt * (16 * SK * 2) + ks * 2);
            #pragma unroll
            for (int mt = 0; mt < 4; ++mt)
                #pragma unroll
                for (int nt = 0; nt < 4; ++nt)
                    mma_bf16(acc[mt][nt], af[mt],
                             bhf[nt >> 1][(nt & 1) * 2],
                             bhf[nt >> 1][(nt & 1) * 2 + 1]);
        }
        // NOTE: no bottom barrier — the next iter's CP_WAIT + __syncthreads
        // orders all readers of stage s before its prefetch overwrite.
    }

    #pragma unroll
    for (int mt = 0; mt < 4; ++mt) {
        const int r1 = row0 + wm * 64 + mt * 16 + (lane >> 2);
        const int r2 = r1 + 8;
        #pragma unroll
        for (int nt = 0; nt < 4; ++nt) {
            const int c = col0 + wn * 32 + nt * 8 + (lane & 3) * 2;
            const float b0 = bias[c], b1 = bias[c + 1];
            const float v0 = acc[mt][nt][0] + b0, v1 = acc[mt][nt][1] + b1;
            const float v2 = acc[mt][nt][2] + b0, v3 = acc[mt][nt][3] + b1;
            if (SPLIT_OUT) {
                uint32_t hi, lo;
                split2(v0, v1, hi, lo);
                *(uint32_t*)(Ch + (size_t)r1 * DM + c) = hi;
                *(uint32_t*)(Cl + (size_t)r1 * DM + c) = lo;
                split2(v2, v3, hi, lo);
                *(uint32_t*)(Ch + (size_t)r2 * DM + c) = hi;
                *(uint32_t*)(Cl + (size_t)r2 * DM + c) = lo;
            } else {
                *(float2*)(C + (size_t)r1 * DM + c) = make_float2(v0, v1);
                *(float2*)(C + (size_t)r2 * DM + c) = make_float2(v2, v3);
            }
        }
    }
}

// ===========================================================================
// HMMA flash attention with relative-position bias.
// K/V/PE smem fills now via cp.async (LDGSTS), shortening the serial
// pre-barrier fill phase of every kv-tile.
// ===========================================================================
#define ATT_SMEM_BYTES (6 * 64 * 72 * 2 + 128 * 72 * 2 + 64 * 136 * 4)

__global__ __launch_bounds__(128)
void rel_attn_hmma_kernel(const bf16* __restrict__ Qhg,
                          const bf16* __restrict__ Qlg,
                          const bf16* __restrict__ Khg,
                          const bf16* __restrict__ Klg,
                          const bf16* __restrict__ VhTg,
                          const bf16* __restrict__ VlTg,
                          const bf16* __restrict__ PEhg,
                          bf16* __restrict__ AOh,
                          bf16* __restrict__ AOl)
{
    extern __shared__ char smx[];
    bf16* sQh = (bf16*)smx;
    bf16* sQl = sQh + 64 * 72;
    bf16* sKh = sQl + 64 * 72;
    bf16* sKl = sKh + 64 * 72;
    bf16* sVh = sKl + 64 * 72;   // V^T: [d][j]
    bf16* sVl = sVh + 64 * 72;
    bf16* sPE = sVl + 64 * 72;   // [128][72]
    float* sQPE = (float*)(sPE + 128 * 72);  // [64][136]

    const uint32_t uSKh = smem_to_u32(sKh);
    const uint32_t uSKl = smem_to_u32(sKl);
    const uint32_t uSVh = smem_to_u32(sVh);
    const uint32_t uSVl = smem_to_u32(sVl);
    const uint32_t uSPE = smem_to_u32(sPE);

    const int tid  = threadIdx.x;
    const int lane = tid & 31;
    const int w    = tid >> 5;
    const int qt   = (int)gridDim.x - 1 - (int)blockIdx.x;
    const int l0   = qt * 64;
    const int n    = blockIdx.y >> 4;
    const int h    = blockIdx.y & 15;

    {
        const bf16* qh = Qhg + ((size_t)(n * LL + l0)) * DM + h * DH;
        const bf16* ql = Qlg + ((size_t)(n * LL + l0)) * DM + h * DH;
        for (int t = tid; t < 64 * 8; t += 128) {
            int r = t >> 3, c8 = (t & 7) * 8;
            *(uint4*)(sQh + r * 72 + c8) = *(const uint4*)(qh + (size_t)r * DM + c8);
            *(uint4*)(sQl + r * 72 + c8) = *(const uint4*)(ql + (size_t)r * DM + c8);
        }
    }
    __syncthreads();

    const int aRow = w * 16 + ((lane >> 3) & 1) * 8 + (lane & 7);
    const int aK   = ((lane >> 4) & 1) * 8;
    const int bRow = ((lane >> 4) & 1) * 8 + (lane & 7);
    const int bK   = ((lane >> 3) & 1) * 8;

    uint32_t qh[4][4], ql[4][4];
    {
        const uint32_t uQh = smem_to_u32(sQh + aRow * 72 + aK);
        const uint32_t uQl = smem_to_u32(sQl + aRow * 72 + aK);
        #pragma unroll
        for (int ks = 0; ks < 4; ++ks) {
            LDMX4(qh[ks], uQh + ks * 32);
            LDMX4(ql[ks], uQl + ks * 32);
        }
    }

    float o[8][4];
    #pragma unroll
    for (int i = 0; i < 8; ++i)
        #pragma unroll
        for (int j = 0; j < 4; ++j) o[i][j] = 0.f;
    float m0 = -1e30f, m1 = -1e30f, ls0acc = 0.f, ls1acc = 0.f;

    const int r0q = lane >> 2, c0 = (lane & 3) * 2;
    const int il0 = w * 16 + r0q, il1 = il0 + 8;
    const float* qpe0 = sQPE + il0 * 136 + 63 - il0;
    const float* qpe1 = sQPE + il1 * 136 + 63 - il1;
    float* qw0 = sQPE + il0 * 136 + c0;
    float* qw1 = sQPE + il1 * 136 + c0;

    for (int jt = 0; jt <= qt; ++jt) {
        const int j0 = jt * 64;

        // ---- K / V^T / PE fills via cp.async ----
        {
            const bf16* kh = Khg + ((size_t)(n * LL + j0)) * DM + h * DH;
            const bf16* kl = Klg + ((size_t)(n * LL + j0)) * DM + h * DH;
            const bf16* vh = VhTg + ((size_t)((n * HH + h) * DH)) * LL + j0;
            const bf16* vl = VlTg + ((size_t)((n * HH + h) * DH)) * LL + j0;
            for (int t = tid; t < 64 * 8; t += 128) {
                int r = t >> 3, c8 = (t & 7) * 8;
                uint32_t so = (uint32_t)(r * 72 + c8) * 2;
                cpa16(uSKh + so, kh + (size_t)r * DM + c8);
                cpa16(uSKl + so, kl + (size_t)r * DM + c8);
                cpa16(uSVh + so, vh + (size_t)r * LL + c8);
                cpa16(uSVl + so, vl + (size_t)r * LL + c8);
            }
            const int pebase = 1984 - l0 + j0;
            for (int t = tid; t < 128 * 8; t += 128) {
                int r = t >> 3, c8 = (t & 7) * 8;
                int gr = pebase + r;
                if (gr < 2048)
                    cpa16(uSPE + (uint32_t)(r * 72 + c8) * 2,
                          PEhg + (size_t)gr * DH + c8);
                else
                    *(uint4*)(sPE + r * 72 + c8) = make_uint4(0u, 0u, 0u, 0u);
            }
            CP_COMMIT();
            CP_WAIT(0);
        }
        __syncthreads();

        // ---- QPE = Qh @ PEband^T ----
        {
            float pacc[16][4];
            #pragma unroll
            for (int i = 0; i < 16; ++i)
                #pragma unroll
                for (int j = 0; j < 4; ++j) pacc[i][j] = 0.f;
            const uint32_t uPE = uSPE + (uint32_t)(bRow * 72 + bK) * 2;
            #pragma unroll
            for (int ks = 0; ks < 4; ++ks) {
                uint32_t pf[8][4];
                #pragma unroll
                for (int p = 0; p < 8; ++p)
                    LDMX4(pf[p], uPE + p * (16 * 72 * 2) + ks * 32);
                #pragma unroll
                for (int nt = 0; nt < 16; ++nt)
                    mma_bf16(pacc[nt], qh[ks],
                             pf[nt >> 1][(nt & 1) * 2],
                             pf[nt >> 1][(nt & 1) * 2 + 1]);
            }
            #pragma unroll
            for (int nt = 0; nt < 16; ++nt) {
                qw0[nt * 8]     = pacc[nt][0];
                qw0[nt * 8 + 1] = pacc[nt][1];
                qw1[nt * 8]     = pacc[nt][2];
                qw1[nt * 8 + 1] = pacc[nt][3];
            }
            __syncwarp();
        }

        // ---- S = Q K^T (3 passes, pass-major) ----
        float s[8][4];
        #pragma unroll
        for (int i = 0; i < 8; ++i)
            #pragma unroll
            for (int j = 0; j < 4; ++j) s[i][j] = 0.f;
        {
            const uint32_t uKh = uSKh + (uint32_t)(bRow * 72 + bK) * 2;
            const uint32_t uKl = uSKl + (uint32_t)(bRow * 72 + bK) * 2;
            #pragma unroll
            for (int ks = 0; ks < 4; ++ks) {
                uint32_t kh[4][4], kl[4][4];
                #pragma unroll
                for (int p = 0; p < 4; ++p) {
                    LDMX4(kh[p], uKh + p * (16 * 72 * 2) + ks * 32);
                    LDMX4(kl[p], uKl + p * (16 * 72 * 2) + ks * 32);
                }
                #pragma unroll
                for (int nt = 0; nt < 8; ++nt)
                    mma_bf16(s[nt], qh[ks], kh[nt >> 1][(nt & 1) * 2],
                             kh[nt >> 1][(nt & 1) * 2 + 1]);
                #pragma unroll
                for (int nt = 0; nt < 8; ++nt)
                    mma_bf16(s[nt], qh[ks], kl[nt >> 1][(nt & 1) * 2],
                             kl[nt >> 1][(nt & 1) * 2 + 1]);
                #pragma unroll
                for (int nt = 0; nt < 8; ++nt)
                    mma_bf16(s[nt], ql[ks], kh[nt >> 1][(nt & 1) * 2],
                             kh[nt >> 1][(nt & 1) * 2 + 1]);
            }
        }

        // ---- bias + scale + mask + online softmax ----
        const bool bd = (jt == qt);
        float rmax0 = -1e30f, rmax1 = -1e30f;
        #pragma unroll
        for (int nt = 0; nt < 8; ++nt) {
            #pragma unroll
            for (int e = 0; e < 2; ++e) {
                const int jl = nt * 8 + c0 + e;
                float v0 = (s[nt][e] + qpe0[jl]) * 0.125f;
                if (bd && jl > il0) v0 = -1e9f;
                s[nt][e] = v0;
                rmax0 = fmaxf(rmax0, v0);
                float v1 = (s[nt][e + 2] + qpe1[jl]) * 0.125f;
                if (bd && jl > il1) v1 = -1e9f;
                s[nt][e + 2] = v1;
                rmax1 = fmaxf(rmax1, v1);
            }
        }
        rmax0 = fmaxf(rmax0, __shfl_xor_sync(0xffffffffu, rmax0, 1));
        rmax0 = fmaxf(rmax0, __shfl_xor_sync(0xffffffffu, rmax0, 2));
        rmax1 = fmaxf(rmax1, __shfl_xor_sync(0xffffffffu, rmax1, 1));
        rmax1 = fmaxf(rmax1, __shfl_xor_sync(0xffffffffu, rmax1, 2));

        const float mn0 = fmaxf(m0, rmax0), mn1 = fmaxf(m1, rmax1);
        const float a0 = fast_exp(m0 - mn0), a1 = fast_exp(m1 - mn1);
        m0 = mn0; m1 = mn1;

        float ls0 = 0.f, ls1 = 0.f;
        uint32_t pah[4][4], pal[4][4];
        #pragma unroll
        for (int nt = 0; nt < 8; ++nt) {
            float p0 = fast_exp(s[nt][0] - m0);
            float p1 = fast_exp(s[nt][1] - m0);
            float p2 = fast_exp(s[nt][2] - m1);
            float p3 = fast_exp(s[nt][3] - m1);
            ls0 += p0 + p1; ls1 += p2 + p3;
            const int kt = nt >> 1, off = (nt & 1) * 2;
            uint32_t hi01, lo01, hi23, lo23;
            split2(p0, p1, hi01, lo01);
            split2(p2, p3, hi23, lo23);
            pah[kt][off]     = hi01;
            pah[kt][off + 1] = hi23;
            pal[kt][off]     = lo01;
            pal[kt][off + 1] = lo23;
        }
        ls0acc = ls0acc * a0 + ls0;
        ls1acc = ls1acc * a1 + ls1;
        #pragma unroll
        for (int nt = 0; nt < 8; ++nt) {
            o[nt][0] *= a0; o[nt][1] *= a0;
            o[nt][2] *= a1; o[nt][3] *= a1;
        }

        // ---- O += P V (3 passes, pass-major) ----
        {
            const uint32_t uVh = uSVh + (uint32_t)(bRow * 72 + bK) * 2;
            const uint32_t uVl = uSVl + (uint32_t)(bRow * 72 + bK) * 2;
            #pragma unroll
            for (int kt = 0; kt < 4; ++kt) {
                uint32_t vh[4][4], vl[4][4];
                #pragma unroll
                for (int p = 0; p < 4; ++p) {
                    LDMX4(vh[p], uVh + p * (16 * 72 * 2) + kt * 32);
                    LDMX4(vl[p], uVl + p * (16 * 72 * 2) + kt * 32);
                }
                #pragma unroll
                for (int dt = 0; dt < 8; ++dt)
                    mma_bf16(o[dt], pah[kt], vh[dt >> 1][(dt & 1) * 2],
                             vh[dt >> 1][(dt & 1) * 2 + 1]);
                #pragma unroll
                for (int dt = 0; dt < 8; ++dt)
                    mma_bf16(o[dt], pah[kt], vl[dt >> 1][(dt & 1) * 2],
                             vl[dt >> 1][(dt & 1) * 2 + 1]);
                #pragma unroll
                for (int dt = 0; dt < 8; ++dt)
                    mma_bf16(o[dt], pal[kt], vh[dt >> 1][(dt & 1) * 2],
                             vh[dt >> 1][(dt & 1) * 2 + 1]);
            }
        }
        __syncthreads();
    }

    // ---- epilogue ----
    float lt0 = ls0acc, lt1 = ls1acc;
    lt0 += __shfl_xor_sync(0xffffffffu, lt0, 1);
    lt0 += __shfl_xor_sync(0xffffffffu, lt0, 2);
    lt1 += __shfl_xor_sync(0xffffffffu, lt1, 1);
    lt1 += __shfl_xor_sync(0xffffffffu, lt1, 2);
    const float inv0 = 1.0f / lt0, inv1 = 1.0f / lt1;
    bf16* oh0 = AOh + ((size_t)(n * LL + l0 + il0)) * DM + h * DH;
    bf16* ol0 = AOl + ((size_t)(n * LL + l0 + il0)) * DM + h * DH;
    bf16* oh1 = AOh + ((size_t)(n * LL + l0 + il1)) * DM + h * DH;
    bf16* ol1 = AOl + ((size_t)(n * LL + l0 + il1)) * DM + h * DH;
    #pragma unroll
    for (int nt = 0; nt < 8; ++nt) {
        uint32_t hi, lo;
        split2(o[nt][0] * inv0, o[nt][1] * inv0, hi, lo);
        *(uint32_t*)(oh0 + nt * 8 + c0) = hi;
        *(uint32_t*)(ol0 + nt * 8 + c0) = lo;
        split2(o[nt][2] * inv1, o[nt][3] * inv1, hi, lo);
        *(uint32_t*)(oh1 + nt * 8 + c0) = hi;
        *(uint32_t*)(ol1 + nt * 8 + c0) = lo;
    }
}

// ===========================================================================
extern "C" void kernel_launch(void* const* d_in, const int* in_sizes, int n_in,
                              void* d_out, int out_size)
{
    const float* q_in = (const float*)d_in[0];
    const float* k_in = (const float*)d_in[1];
    const float* v_in = (const float*)d_in[2];
    const float* Wq = (const float*)d_in[4];
    const float* bq = (const float*)d_in[5];
    const float* Wk = (const float*)d_in[6];
    const float* bk = (const float*)d_in[7];
    const float* Wv = (const float*)d_in[8];
    const float* bv = (const float*)d_in[9];
    const float* Wo = (const float*)d_in[10];
    const float* bo = (const float*)d_in[11];
    const float* pe = (const float*)d_in[12];
    float* out = (float*)d_out;

    bf16 *Ahp, *Alp, *BhTp, *BlTp, *QKVhp, *QKVlp;
    bf16 *VhTp, *VlTp, *AOhp, *AOlp, *PEhp;
    cudaGetSymbolAddress((void**)&Ahp,   g_Ah);
    cudaGetSymbolAddress((void**)&Alp,   g_Al);
    cudaGetSymbolAddress((void**)&BhTp,  g_BhT);
    cudaGetSymbolAddress((void**)&BlTp,  g_BlT);
    cudaGetSymbolAddress((void**)&QKVhp, g_QKVh);
    cudaGetSymbolAddress((void**)&QKVlp, g_QKVl);
    cudaGetSymbolAddress((void**)&VhTp,  g_VhT);
    cudaGetSymbolAddress((void**)&VlTp,  g_VlT);
    cudaGetSymbolAddress((void**)&AOhp,  g_AOh);
    cudaGetSymbolAddress((void**)&AOlp,  g_AOl);
    cudaGetSymbolAddress((void**)&PEhp,  g_PEh);

    cudaFuncSetAttribute(rel_attn_hmma_kernel,
                         cudaFuncAttributeMaxDynamicSharedMemorySize,
                         ATT_SMEM_BYTES);
    cudaFuncSetAttribute(hmma_gemm_kernel<0>,
                         cudaFuncAttributeMaxDynamicSharedMemorySize,
                         GEMM_SMEM);
    cudaFuncSetAttribute(hmma_gemm_kernel<1>,
                         cudaFuncAttributeMaxDynamicSharedMemorySize,
                         GEMM_SMEM);

    const int nA = MROWS * DM;
    const dim3 sp_grid(nA / 4 / 256, 1, 3);
    const dim3 tr_blk(32, 8);
    const dim3 mm_grid3(DM / 128, MROWS / 128, 3);
    const dim3 mm_grid1(DM / 128, MROWS / 128, 1);
    const dim3 vt_grid(LL / 32, DH / 32, NB * HH);

    pe_split_kernel<<<2048 * DH / 4 / 256, 256>>>(pe, PEhp);

    // fused Q/K/V projection chain
    split3_kernel<<<sp_grid, 256>>>(q_in, k_in, v_in, Ahp, Alp, nA);
    splitT3_kernel<<<dim3(DM / 32, DM / 32, 3), tr_blk>>>(Wq, Wk, Wv,
                                                          BhTp, BlTp);
    hmma_gemm_kernel<1><<<mm_grid3, 256, GEMM_SMEM>>>(
        Ahp, Alp, BhTp, BlTp, bq, bk, bv, nullptr, QKVhp, QKVlp);

    vtrans_kernel<<<vt_grid, dim3(32, 8)>>>(QKVhp + 2 * MA, QKVlp + 2 * MA,
                                            VhTp, VlTp);

    rel_attn_hmma_kernel<<<dim3(LL / 64, NB * HH), 128, ATT_SMEM_BYTES>>>(
        QKVhp, QKVlp, QKVhp + MA, QKVlp + MA, VhTp, VlTp, PEhp, AOhp, AOlp);

    // out = AO @ Wo + bo
    splitT3_kernel<<<dim3(DM / 32, DM / 32, 1), tr_blk>>>(Wo, Wo, Wo,
                                                          BhTp, BlTp);
    hmma_gemm_kernel<0><<<mm_grid1, 256, GEMM_SMEM>>>(
        AOhp, AOlp, BhTp, BlTp, bo, bo, bo, out, nullptr, nullptr);
}